// round 12
// baseline (speedup 1.0000x reference)
#include <cuda_runtime.h>
#include <cuda_bf16.h>
#include <cuda_fp16.h>
#include <mma.h>
#include <cstdint>

#define NN 50000
#define NE 800000
#define HID 128
#define LATD 64
#define IN_NODE 11
#define IN_EDGE 4
#define NB_SCAN 98   // ceil(50000/512)

// ---------------- device scratch ----------------
__device__ float g_h0buf[NN * HID];
__device__ float g_h1buf[NN * HID];
__device__ float g_agg[NN * HID];
__device__ __half g_P1h[NN * HID];    // fp16 P tables (halved gather traffic)
__device__ __half g_P2h[NN * HID];
__device__ float g_nf[NN * HID];
// counting-sort scratch
__device__ int g_cnt[NN];
__device__ int g_off[NB_SCAN * 512];
__device__ int g_cur[NN];
__device__ int g_blksum[NB_SCAN];
__device__ int g_blkoff[NB_SCAN];
// permuted (row-sorted) edge arrays
__device__ int   g_rowS[NE];
__device__ int   g_colS[NE];
__device__ float g_radS[NE];
__device__ float4 g_eaS[NE];
// fp16 weights: edge W2, ew1 rows 0..255 (two [128][128] per layer)
__device__ __half g_Wf16[2][HID * HID];
__device__ __half g_E1f16[2][2][HID * HID];
// bf16 hi/lo weight splits (node GEMMs only)
__device__ __nv_bfloat16 g_N1h[2][2 * HID * HID];     // [wsum ; W1b] [256][128]
__device__ __nv_bfloat16 g_N1l[2][2 * HID * HID];
__device__ __nv_bfloat16 g_N2h[2][HID * HID];         // nw2 [128][128]
__device__ __nv_bfloat16 g_N2l[2][HID * HID];

__device__ __forceinline__ float elu(float v) {
    return v > 0.f ? v : (__expf(v) - 1.f);
}

__device__ __forceinline__ void red4(float* p, float a, float b, float c, float d) {
    asm volatile("red.global.add.v4.f32 [%0], {%1,%2,%3,%4};"
                 :: "l"(p), "f"(a), "f"(b), "f"(c), "f"(d) : "memory");
}

__device__ __forceinline__ uint32_t pack_bf16(float e0, float e1) {
    uint32_t r;
    asm("cvt.rn.bf16x2.f32 %0, %1, %2;" : "=r"(r) : "f"(e1), "f"(e0));
    return r;
}

// cp.async helpers (16B)
__device__ __forceinline__ void cp16(void* smem_dst, const void* gsrc) {
    uint32_t d = (uint32_t)__cvta_generic_to_shared(smem_dst);
    asm volatile("cp.async.ca.shared.global [%0], [%1], 16;" :: "r"(d), "l"(gsrc) : "memory");
}
#define CP_COMMIT() asm volatile("cp.async.commit_group;" ::: "memory")
#define CP_WAIT0()  asm volatile("cp.async.wait_group 0;" ::: "memory")

// ---------------- small kernels ----------------
__global__ void embed_kernel(const float* __restrict__ h0,
                             const float* __restrict__ emb_w,
                             const float* __restrict__ emb_b) {
    int idx = blockIdx.x * 256 + threadIdx.x;
    if (idx >= NN * HID) return;
    int n = idx >> 7, j = idx & 127;
    float acc = emb_b[j];
#pragma unroll
    for (int k = 0; k < IN_NODE; k++)
        acc += h0[n * IN_NODE + k] * emb_w[k * HID + j];
    g_h0buf[idx] = acc;
}

__global__ void zero_agg_kernel() {
    int i = blockIdx.x * 256 + threadIdx.x;
    if (i < NN * HID / 4)
        ((float4*)g_agg)[i] = make_float4(0.f, 0.f, 0.f, 0.f);
}

// fp16 weight prep: edge W2 [K][N] + ew1 rows 0..255
__global__ void wf16prep_kernel(const float* __restrict__ ew2,
                                const float* __restrict__ ew1) {
    int idx = blockIdx.x * 256 + threadIdx.x;
    if (idx >= 98304) return;
    if (idx < 32768) {
        int layer = idx >> 14, rem = idx & 16383;
        g_Wf16[layer][rem] = __float2half(ew2[layer * HID * HID + rem]);
    } else {
        int t = idx - 32768;
        int l = t >> 15, rest = t & 32767;
        int y = rest >> 14, r2 = rest & 16383;
        g_E1f16[l][y][r2] =
            __float2half(ew1[(l * 261 + y * 128 + (r2 >> 7)) * 128 + (r2 & 127)]);
    }
}

// split node W1 (wsum-folded) and node W2 into bf16 hi/lo
__global__ void prep_split_kernel(const float* __restrict__ nw1,
                                  const float* __restrict__ nw2) {
    int idx = blockIdx.x * 256 + threadIdx.x;
    if (idx >= 98304) return;
    float v;
    __nv_bfloat16 *dh, *dl;
    if (idx < 65536) {
        int l = idx >> 15, rest = idx & 32767;
        int k = rest >> 7, j = rest & 127;
        if (k < 128)
            v = nw1[(l * 384 + k) * 128 + j] + nw1[(l * 384 + 256 + k) * 128 + j];
        else
            v = nw1[(l * 384 + 128 + (k - 128)) * 128 + j];
        dh = &g_N1h[l][rest];
        dl = &g_N1l[l][rest];
    } else {
        int t = idx - 65536;
        int l = t >> 14, rest = t & 16383;
        v = nw2[l * 16384 + rest];
        dh = &g_N2h[l][rest];
        dl = &g_N2l[l][rest];
    }
    __nv_bfloat16 hb = __float2bfloat16(v);
    *dh = hb;
    *dl = __float2bfloat16(v - __bfloat162float(hb));
}

// ---------------- counting sort of edges by row ----------------
__global__ void sort_zero_kernel() {
    int i = blockIdx.x * 256 + threadIdx.x;
    if (i < NN) g_cnt[i] = 0;
}

__global__ void sort_hist_kernel(const int* __restrict__ row) {
    int e = blockIdx.x * 256 + threadIdx.x;
    if (e < NE) atomicAdd(&g_cnt[row[e]], 1);
}

__global__ void sort_scan1_kernel() {
    __shared__ int buf[512];
    int t = threadIdx.x;
    int i = blockIdx.x * 512 + t;
    int v = (i < NN) ? g_cnt[i] : 0;
    buf[t] = v;
    __syncthreads();
#pragma unroll
    for (int d = 1; d < 512; d <<= 1) {
        int x = (t >= d) ? buf[t - d] : 0;
        __syncthreads();
        buf[t] += x;
        __syncthreads();
    }
    g_off[i] = buf[t] - v;
    if (t == 511) g_blksum[blockIdx.x] = buf[511];
}

__global__ void sort_scan2_kernel() {
    if (threadIdx.x == 0) {
        int s = 0;
        for (int k = 0; k < NB_SCAN; k++) {
            g_blkoff[k] = s;
            s += g_blksum[k];
        }
    }
}

__global__ void sort_scan3_kernel() {
    int i = blockIdx.x * 256 + threadIdx.x;
    if (i < NN) {
        int o = g_off[i] + g_blkoff[i >> 9];
        g_off[i] = o;
        g_cur[i] = o;
    }
}

__global__ void sort_scatter_kernel(const int* __restrict__ row,
                                    const int* __restrict__ col,
                                    const float* __restrict__ x,
                                    const float* __restrict__ edge_attr) {
    int e = blockIdx.x * 256 + threadIdx.x;
    if (e >= NE) return;
    int r = row[e], c = col[e];
    float dx = x[r * 3 + 0] - x[c * 3 + 0];
    float dy = x[r * 3 + 1] - x[c * 3 + 1];
    float dz = x[r * 3 + 2] - x[c * 3 + 2];
    float rad = dx * dx + dy * dy + dz * dz;
    int pos = atomicAdd(&g_cur[r], 1);
    g_rowS[pos] = r;
    g_colS[pos] = c;
    g_radS[pos] = rad;
    g_eaS[pos] = *(const float4*)(edge_attr + (size_t)e * 4);
}

// ---------------- pre kernel: single-pass fp16 GEMM, P = h @ E1 (fp16 out) ----------------
static constexpr int PF_ST = 136;   // fp16 stride
static constexpr int PF_DST = 132;  // f32 stride, D (unions A+B)
static constexpr int PRE_SMEM = 69632;  // A 34816 + B 34816; D 67584 unions at 0

__global__ void __launch_bounds__(256, 2)
pre_f16_kernel(const float* __restrict__ hsrc,
               const __half* __restrict__ B1, __half* __restrict__ P1,
               const __half* __restrict__ B2, __half* __restrict__ P2) {
    extern __shared__ char smem[];
    __half* sA = (__half*)smem;
    __half* sB = (__half*)(smem + 34816);
    float* sD  = (float*)smem;

    const __half* B = (blockIdx.y == 0) ? B1 : B2;
    __half* P = (blockIdx.y == 0) ? P1 : P2;

    int tid = threadIdx.x;
    int wid = tid >> 5;
    int n0 = blockIdx.x * 128;
    int r = tid >> 1, hf = tid & 1;
    int n = n0 + r;

    // prefetch full B [128][128] fp16
    {
#pragma unroll
        for (int it = 0; it < 8; it++) {
            int i = tid + it * 256;
            int k = i >> 4, u = i & 15;
            cp16(sB + k * PF_ST + u * 8, B + (size_t)k * HID + u * 8);
        }
        CP_COMMIT();
    }

    // stage A: fp32 h -> fp16
    if (n < NN) {
#pragma unroll
        for (int q = 0; q < 16; q++) {
            int col = hf * 64 + q * 4;
            float4 v = *(const float4*)(hsrc + (size_t)n * HID + col);
            __half2* pa = (__half2*)(sA + r * PF_ST + col);
            pa[0] = __floats2half2_rn(v.x, v.y);
            pa[1] = __floats2half2_rn(v.z, v.w);
        }
    } else {
#pragma unroll
        for (int q = 0; q < 16; q++) {
            int col = hf * 64 + q * 4;
            __half2* pa = (__half2*)(sA + r * PF_ST + col);
            pa[0] = __half2half2(__float2half(0.f));
            pa[1] = __half2half2(__float2half(0.f));
        }
    }
    CP_WAIT0();
    __syncthreads();

    using namespace nvcuda::wmma;
    {
        int m0 = wid * 16;
        fragment<accumulator, 16, 16, 16, float> acc[8];
#pragma unroll
        for (int j = 0; j < 8; j++) fill_fragment(acc[j], 0.f);
#pragma unroll
        for (int k = 0; k < 8; k++) {
            fragment<matrix_a, 16, 16, 16, __half, row_major> a;
            load_matrix_sync(a, sA + m0 * PF_ST + k * 16, PF_ST);
#pragma unroll
            for (int nf = 0; nf < 8; nf++) {
                fragment<matrix_b, 16, 16, 16, __half, row_major> b;
                load_matrix_sync(b, sB + (k * 16) * PF_ST + nf * 16, PF_ST);
                mma_sync(acc[nf], a, b, acc[nf]);
            }
        }
        __syncthreads();
#pragma unroll
        for (int nf = 0; nf < 8; nf++)
            store_matrix_sync(sD + m0 * PF_DST + nf * 16, acc[nf], PF_DST, mem_row_major);
    }
    __syncthreads();

    if (n < NN) {
#pragma unroll
        for (int q = 0; q < 16; q++) {
            int col = hf * 64 + q * 4;
            float4 v = *(const float4*)(sD + r * PF_DST + col);
            __half2* po = (__half2*)(P + (size_t)n * HID + col);
            po[0] = __floats2half2_rn(v.x, v.y);
            po[1] = __floats2half2_rn(v.z, v.w);
        }
    }
}

// ---------------- generic dense GEMM (bf16 3-pass, cp.async): node GEMMs ----------------
static constexpr int GA_ST = 72;
static constexpr int GB_ST = 136;
static constexpr int GD_ST = 132;
static constexpr int G_SAH = 0;
static constexpr int G_SAL = 18432;
static constexpr int G_SBH = 36864;
static constexpr int G_SBL = 54272;
static constexpr int GEMM_SMEM = 71680;

__global__ void __launch_bounds__(256, 2)
gemm_wmma_kernel(const float* __restrict__ A0, const float* __restrict__ A1,
                 int k64,
                 const __nv_bfloat16* __restrict__ Bh,
                 const __nv_bfloat16* __restrict__ Bl,
                 const float* __restrict__ bias,
                 float* __restrict__ out, int do_elu) {
    extern __shared__ char smem[];
    __nv_bfloat16* sAh = (__nv_bfloat16*)(smem + G_SAH);
    __nv_bfloat16* sAl = (__nv_bfloat16*)(smem + G_SAL);
    __nv_bfloat16* sBh = (__nv_bfloat16*)(smem + G_SBH);
    __nv_bfloat16* sBl = (__nv_bfloat16*)(smem + G_SBL);
    float* sD = (float*)smem;

    int tid = threadIdx.x;
    int wid = tid >> 5;
    int n0 = blockIdx.x * 128;
    int r = tid >> 1, hf = tid & 1;
    int n = n0 + r;

    using namespace nvcuda::wmma;
    fragment<accumulator, 16, 16, 16, float> acc[8];
#pragma unroll
    for (int j = 0; j < 8; j++) fill_fragment(acc[j], 0.f);

    for (int c = 0; c < k64; c++) {
        {
#pragma unroll
            for (int it = 0; it < 4; it++) {
                int i = tid + it * 256;
                int kb = i >> 4, u = i & 15;
                cp16(sBh + kb * GB_ST + u * 8, Bh + (size_t)(c * 64 + kb) * HID + u * 8);
                cp16(sBl + kb * GB_ST + u * 8, Bl + (size_t)(c * 64 + kb) * HID + u * 8);
            }
            CP_COMMIT();
        }
        {
            const float* src = (c < 2) ? A0 : A1;
            int kbase = (c & 1) * 64;
            if (n < NN) {
#pragma unroll
                for (int q = 0; q < 8; q++) {
                    int col = hf * 32 + q * 4;
                    float4 v = *(const float4*)(src + (size_t)n * HID + kbase + col);
                    float h0f = __bfloat162float(__float2bfloat16(v.x));
                    float h1f = __bfloat162float(__float2bfloat16(v.y));
                    float h2f = __bfloat162float(__float2bfloat16(v.z));
                    float h3f = __bfloat162float(__float2bfloat16(v.w));
                    uint32_t* ph = (uint32_t*)(sAh + r * GA_ST + col);
                    uint32_t* pl = (uint32_t*)(sAl + r * GA_ST + col);
                    ph[0] = pack_bf16(h0f, h1f);
                    ph[1] = pack_bf16(h2f, h3f);
                    pl[0] = pack_bf16(v.x - h0f, v.y - h1f);
                    pl[1] = pack_bf16(v.z - h2f, v.w - h3f);
                }
            } else {
#pragma unroll
                for (int q = 0; q < 8; q++) {
                    int col = hf * 32 + q * 4;
                    uint32_t* ph = (uint32_t*)(sAh + r * GA_ST + col);
                    uint32_t* pl = (uint32_t*)(sAl + r * GA_ST + col);
                    ph[0] = 0; ph[1] = 0; pl[0] = 0; pl[1] = 0;
                }
            }
        }
        CP_WAIT0();
        __syncthreads();

        {
            int m0 = wid * 16;
#pragma unroll
            for (int kf = 0; kf < 4; kf++) {
                fragment<matrix_a, 16, 16, 16, __nv_bfloat16, row_major> ah, al;
                load_matrix_sync(ah, sAh + m0 * GA_ST + kf * 16, GA_ST);
                load_matrix_sync(al, sAl + m0 * GA_ST + kf * 16, GA_ST);
#pragma unroll
                for (int nf = 0; nf < 8; nf++) {
                    fragment<matrix_b, 16, 16, 16, __nv_bfloat16, row_major> b;
                    load_matrix_sync(b, sBh + (kf * 16) * GB_ST + nf * 16, GB_ST);
                    mma_sync(acc[nf], ah, b, acc[nf]);
                    mma_sync(acc[nf], al, b, acc[nf]);
                }
            }
#pragma unroll
            for (int kf = 0; kf < 4; kf++) {
                fragment<matrix_a, 16, 16, 16, __nv_bfloat16, row_major> ah;
                load_matrix_sync(ah, sAh + m0 * GA_ST + kf * 16, GA_ST);
#pragma unroll
                for (int nf = 0; nf < 8; nf++) {
                    fragment<matrix_b, 16, 16, 16, __nv_bfloat16, row_major> b;
                    load_matrix_sync(b, sBl + (kf * 16) * GB_ST + nf * 16, GB_ST);
                    mma_sync(acc[nf], ah, b, acc[nf]);
                }
            }
        }
        __syncthreads();
    }

    {
        int m0 = wid * 16;
#pragma unroll
        for (int nf = 0; nf < 8; nf++)
            store_matrix_sync(sD + m0 * GD_ST + nf * 16, acc[nf], GD_ST, mem_row_major);
    }
    __syncthreads();

    if (n < NN) {
#pragma unroll
        for (int q = 0; q < 16; q++) {
            int col = hf * 64 + q * 4;
            float4 v = *(const float4*)(sD + r * GD_ST + col);
            if (bias) {
                v.x += bias[col + 0];
                v.y += bias[col + 1];
                v.z += bias[col + 2];
                v.w += bias[col + 3];
            }
            if (do_elu) {
                v.x = elu(v.x); v.y = elu(v.y); v.z = elu(v.z); v.w = elu(v.w);
            }
            *(float4*)(out + (size_t)n * HID + col) = v;
        }
    }
}

// ---------------- edge kernel: single-pass fp16 MMA, fp16 P gather ----------------
static constexpr int AST = 136;   // fp16 stride
static constexpr int DSTR = 132;  // f32 stride, D (unions A+B after MMA)
static constexpr int SM_A  = 0;        // 128*136*2 = 34816
static constexpr int SM_B  = 34816;    // 34816 -> 69632
static constexpr int SM_WT = 69632;    // 5*128*4 = 2560
static constexpr int SM_B1 = 72192;    // 512
static constexpr int SM_B2 = 72704;    // 512
static constexpr int SM_ROW = 73216;   // 512
static constexpr int EDGE_SMEM_BYTES = 73728;

__global__ void __launch_bounds__(256, 2)
edge_hmma_kernel(const float* __restrict__ ew1, const float* __restrict__ eb1,
                 const float* __restrict__ eb2, int layer) {
    extern __shared__ char smem[];
    __half* sA = (__half*)(smem + SM_A);
    __half* sB = (__half*)(smem + SM_B);
    float* sD  = (float*)smem;
    float* sWT = (float*)(smem + SM_WT);
    float* sB1 = (float*)(smem + SM_B1);
    float* sB2 = (float*)(smem + SM_B2);
    int*   sRow = (int*)(smem + SM_ROW);

    int tid = threadIdx.x;
    int wid = tid >> 5;
    int e0 = blockIdx.x * 128;

    // prefetch full B [128k][128n] fp16 via cp.async (hides behind A-build)
    {
        const __half* gW = g_Wf16[layer];
#pragma unroll
        for (int it = 0; it < 8; it++) {
            int i = tid + it * 256;
            int k = i >> 4, u = i & 15;
            cp16(sB + k * AST + u * 8, gW + k * HID + u * 8);
        }
        CP_COMMIT();
    }

    // stage tail weights, biases, sorted rows
    for (int i = tid; i < 5 * HID; i += 256) sWT[i] = ew1[(layer * 261 + 2 * HID) * HID + i];
    if (tid < HID) {
        sB1[tid] = eb1[layer * HID + tid];
        sB2[tid] = eb2[layer * HID + tid];
    }
    if (tid < 128) sRow[tid] = g_rowS[e0 + tid];
    __syncthreads();

    // A-build: elu(P1[row]+P2[col]+rad*w+ea@Wtail+b1) -> fp16 (P gathered as fp16)
    {
        int m = tid >> 1, hf = tid & 1;
        int e = e0 + m;
        int r = sRow[m], c = g_colS[e];
        float rad = g_radS[e];
        float4 ea = g_eaS[e];
        const __half* p1r = g_P1h + (size_t)r * HID;
        const __half* p2r = g_P2h + (size_t)c * HID;
#pragma unroll
        for (int q = 0; q < 16; q++) {
            int jb = hf * 64 + q * 4;
            const __half2* h1 = (const __half2*)(p1r + jb);
            const __half2* h2 = (const __half2*)(p2r + jb);
            float2 p1a = __half22float2(h1[0]), p1b = __half22float2(h1[1]);
            float2 p2a = __half22float2(h2[0]), p2b = __half22float2(h2[1]);
            float4 w0 = *(const float4*)(sWT + 0 * HID + jb);
            float4 w1 = *(const float4*)(sWT + 1 * HID + jb);
            float4 w2 = *(const float4*)(sWT + 2 * HID + jb);
            float4 w3 = *(const float4*)(sWT + 3 * HID + jb);
            float4 w4 = *(const float4*)(sWT + 4 * HID + jb);
            float4 bb = *(const float4*)(sB1 + jb);
            float o0 = elu(p1a.x + p2a.x + rad * w0.x + ea.x * w1.x + ea.y * w2.x + ea.z * w3.x + ea.w * w4.x + bb.x);
            float o1 = elu(p1a.y + p2a.y + rad * w0.y + ea.x * w1.y + ea.y * w2.y + ea.z * w3.y + ea.w * w4.y + bb.y);
            float o2 = elu(p1b.x + p2b.x + rad * w0.z + ea.x * w1.z + ea.y * w2.z + ea.z * w3.z + ea.w * w4.z + bb.z);
            float o3 = elu(p1b.y + p2b.y + rad * w0.w + ea.x * w1.w + ea.y * w2.w + ea.z * w3.w + ea.w * w4.w + bb.w);
            __half2* pa = (__half2*)(sA + m * AST + jb);
            pa[0] = __floats2half2_rn(o0, o1);
            pa[1] = __floats2half2_rn(o2, o3);
        }
    }
    CP_WAIT0();
    __syncthreads();

    // single-pass fp16 MMA: warp wid -> rows [wid*16,+16), all 128 cols
    using namespace nvcuda::wmma;
    {
        int m0 = wid * 16;
        fragment<accumulator, 16, 16, 16, float> acc[8];
#pragma unroll
        for (int j = 0; j < 8; j++) fill_fragment(acc[j], 0.f);

#pragma unroll
        for (int k = 0; k < 8; k++) {
            fragment<matrix_a, 16, 16, 16, __half, row_major> a;
            load_matrix_sync(a, sA + m0 * AST + k * 16, AST);
#pragma unroll
            for (int nf = 0; nf < 8; nf++) {
                fragment<matrix_b, 16, 16, 16, __half, row_major> b;
                load_matrix_sync(b, sB + (k * 16) * AST + nf * 16, AST);
                mma_sync(acc[nf], a, b, acc[nf]);
            }
        }

        __syncthreads();   // A and B fully dead -> D may overwrite
#pragma unroll
        for (int nf = 0; nf < 8; nf++)
            store_matrix_sync(sD + m0 * DSTR + nf * 16, acc[nf], DSTR, mem_row_major);
    }
    __syncthreads();

    // single merged scatter: eg = 8-edge group, ct = 8-col group
    {
        int ct = tid & 15, eg = tid >> 4;
        int jb = ct * 8;
        float b2v[8];
#pragma unroll
        for (int k = 0; k < 8; k++) b2v[k] = sB2[jb + k];
        float run[8];
#pragma unroll
        for (int k = 0; k < 8; k++) run[k] = 0.f;
        int cur = sRow[eg * 8];
#pragma unroll
        for (int i = 0; i < 8; i++) {
            int m = eg * 8 + i;
            int rr = sRow[m];
            if (rr != cur) {
                float* dst = g_agg + (size_t)cur * HID + jb;
                red4(dst, run[0], run[1], run[2], run[3]);
                red4(dst + 4, run[4], run[5], run[6], run[7]);
#pragma unroll
                for (int k = 0; k < 8; k++) run[k] = 0.f;
                cur = rr;
            }
            const float* sd = sD + m * DSTR + jb;
#pragma unroll
            for (int k = 0; k < 8; k++) run[k] += elu(sd[k] + b2v[k]);
        }
        float* dst = g_agg + (size_t)cur * HID + jb;
        red4(dst, run[0], run[1], run[2], run[3]);
        red4(dst + 4, run[4], run[5], run[6], run[7]);
    }
}

// ---------------- final head ----------------
__global__ void final_kernel(const float* __restrict__ label,
                             const float* __restrict__ eps,
                             const float* __restrict__ mu_w, const float* __restrict__ mu_b,
                             const float* __restrict__ var_w, const float* __restrict__ var_b,
                             float* __restrict__ out) {
    int idx = blockIdx.x * 256 + threadIdx.x;
    if (idx >= NN * LATD) return;
    int n = idx >> 6, l = idx & 63;
    float am = mu_b[l], av = var_b[l];
    const float* hrow = g_h0buf + n * HID;
#pragma unroll 4
    for (int k = 0; k < HID; k++) {
        float hv = hrow[k];
        am += hv * mu_w[k * LATD + l];
        av += hv * var_w[k * LATD + l];
    }
#pragma unroll
    for (int c = 0; c < 7; c++) {
        float lv = label[n * 7 + c];
        am += lv * mu_w[(HID + c) * LATD + l];
        av += lv * var_w[(HID + c) * LATD + l];
    }
    out[idx] = am + 0.01f * eps[idx] * __expf(0.5f * av);
}

// ---------------- launch ----------------
extern "C" void kernel_launch(void* const* d_in, const int* in_sizes, int n_in,
                              void* d_out, int out_size) {
    const float* h0        = (const float*)d_in[0];
    const float* label     = (const float*)d_in[1];
    const float* x         = (const float*)d_in[2];
    const float* edge_attr = (const float*)d_in[3];
    const float* eps       = (const float*)d_in[4];
    const float* emb_w     = (const float*)d_in[5];
    const float* emb_b     = (const float*)d_in[6];
    const float* ew1       = (const float*)d_in[7];
    const float* eb1       = (const float*)d_in[8];
    const float* ew2       = (const float*)d_in[9];
    const float* eb2       = (const float*)d_in[10];
    const float* nw1       = (const float*)d_in[11];
    const float* nb1       = (const float*)d_in[12];
    const float* nw2       = (const float*)d_in[13];
    const float* nb2       = (const float*)d_in[14];
    const float* mu_w      = (const float*)d_in[15];
    const float* mu_b      = (const float*)d_in[16];
    const float* var_w     = (const float*)d_in[17];
    const float* var_b     = (const float*)d_in[18];
    const int*   edges     = (const int*)d_in[19];
    const int* rowp = edges;
    const int* colp = edges + NE;
    float* out = (float*)d_out;

    cudaFuncSetAttribute(edge_hmma_kernel, cudaFuncAttributeMaxDynamicSharedMemorySize, EDGE_SMEM_BYTES);
    cudaFuncSetAttribute(gemm_wmma_kernel, cudaFuncAttributeMaxDynamicSharedMemorySize, GEMM_SMEM);
    cudaFuncSetAttribute(pre_f16_kernel, cudaFuncAttributeMaxDynamicSharedMemorySize, PRE_SMEM);

    const int GGRID = (NN + 127) / 128;   // 391

    embed_kernel<<<(NN * HID + 255) / 256, 256>>>(h0, emb_w, emb_b);
    wf16prep_kernel<<<(98304 + 255) / 256, 256>>>(ew2, ew1);
    prep_split_kernel<<<(98304 + 255) / 256, 256>>>(nw1, nw2);

    // counting sort of edges by source node (once per launch)
    sort_zero_kernel<<<(NN + 255) / 256, 256>>>();
    sort_hist_kernel<<<(NE + 255) / 256, 256>>>(rowp);
    sort_scan1_kernel<<<NB_SCAN, 512>>>();
    sort_scan2_kernel<<<1, 32>>>();
    sort_scan3_kernel<<<(NN + 255) / 256, 256>>>();
    sort_scatter_kernel<<<(NE + 255) / 256, 256>>>(rowp, colp, x, edge_attr);

    float *h0p, *h1p, *aggp, *nfp;
    cudaGetSymbolAddress((void**)&h0p, g_h0buf);
    cudaGetSymbolAddress((void**)&h1p, g_h1buf);
    cudaGetSymbolAddress((void**)&aggp, g_agg);
    cudaGetSymbolAddress((void**)&nfp, g_nf);
    __half *p1p, *p2p, *e1f;
    cudaGetSymbolAddress((void**)&p1p, g_P1h);
    cudaGetSymbolAddress((void**)&p2p, g_P2h);
    cudaGetSymbolAddress((void**)&e1f, g_E1f16);
    __nv_bfloat16 *n1h, *n1l, *n2h, *n2l;
    cudaGetSymbolAddress((void**)&n1h, g_N1h);
    cudaGetSymbolAddress((void**)&n1l, g_N1l);
    cudaGetSymbolAddress((void**)&n2h, g_N2h);
    cudaGetSymbolAddress((void**)&n2l, g_N2l);

    for (int layer = 0; layer < 2; layer++) {
        float* hsrc_p = (layer == 0) ? h0p : h1p;
        float* hdst   = (layer == 0) ? h1p : h0p;

        zero_agg_kernel<<<(NN * HID / 4 + 255) / 256, 256>>>();

        // P1 and P2 in one launch (single-pass fp16, fp16 out)
        pre_f16_kernel<<<dim3(GGRID, 2), 256, PRE_SMEM>>>(
            hsrc_p,
            e1f + (size_t)layer * 2 * HID * HID, p1p,
            e1f + ((size_t)layer * 2 + 1) * HID * HID, p2p);

        edge_hmma_kernel<<<NE / 128, 256, EDGE_SMEM_BYTES>>>(ew1, eb1, eb2, layer);

        // node GEMM1: nf = elu([h|agg] @ N1 + nb1)
        gemm_wmma_kernel<<<GGRID, 256, GEMM_SMEM>>>(
            hsrc_p, aggp, 4,
            n1h + (size_t)layer * 2 * HID * HID, n1l + (size_t)layer * 2 * HID * HID,
            nb1 + layer * HID, nfp, 1);
        // node GEMM2: hdst = nf @ N2 + nb2
        gemm_wmma_kernel<<<GGRID, 256, GEMM_SMEM>>>(
            nfp, nullptr, 2,
            n2h + (size_t)layer * HID * HID, n2l + (size_t)layer * HID * HID,
            nb2 + layer * HID, hdst, 0);
    }

    final_kernel<<<(NN * LATD + 255) / 256, 256>>>(label, eps, mu_w, mu_b,
                                                   var_w, var_b, out);
}

// round 13
// speedup vs baseline: 1.2287x; 1.2287x over previous
#include <cuda_runtime.h>
#include <cuda_bf16.h>
#include <cuda_fp16.h>
#include <mma.h>
#include <cstdint>

#define NN 50000
#define NE 800000
#define HID 128
#define LATD 64
#define IN_NODE 11
#define IN_EDGE 4
#define NB_SCAN 98   // ceil(50000/512)

// ---------------- device scratch ----------------
__device__ float g_h0buf[NN * HID];
__device__ float g_h1buf[NN * HID];
__device__ float g_agg[NN * HID];
__device__ __half g_P1h[NN * HID];    // fp16 P tables (halved gather traffic)
__device__ __half g_P2h[NN * HID];
__device__ float g_nf[NN * HID];
// counting-sort scratch
__device__ int g_cnt[NN];
__device__ int g_off[NB_SCAN * 512];
__device__ int g_cur[NN];
__device__ int g_blksum[NB_SCAN];
__device__ int g_blkoff[NB_SCAN];
// permuted (row-sorted) edge arrays
__device__ int   g_rowS[NE];
__device__ int   g_colS[NE];
__device__ float g_radS[NE];
__device__ float4 g_eaS[NE];
// fp16 weights: edge W2, ew1 rows 0..255 (two [128][128] per layer)
__device__ __half g_Wf16[2][HID * HID];
__device__ __half g_E1f16[2][2][HID * HID];
// bf16 hi/lo weight splits (node GEMMs only)
__device__ __nv_bfloat16 g_N1h[2][2 * HID * HID];     // [wsum ; W1b] [256][128]
__device__ __nv_bfloat16 g_N1l[2][2 * HID * HID];
__device__ __nv_bfloat16 g_N2h[2][HID * HID];         // nw2 [128][128]
__device__ __nv_bfloat16 g_N2l[2][HID * HID];

__device__ __forceinline__ float elu(float v) {
    return v > 0.f ? v : (__expf(v) - 1.f);
}

__device__ __forceinline__ void red4(float* p, float a, float b, float c, float d) {
    asm volatile("red.global.add.v4.f32 [%0], {%1,%2,%3,%4};"
                 :: "l"(p), "f"(a), "f"(b), "f"(c), "f"(d) : "memory");
}

__device__ __forceinline__ uint32_t pack_bf16(float e0, float e1) {
    uint32_t r;
    asm("cvt.rn.bf16x2.f32 %0, %1, %2;" : "=r"(r) : "f"(e1), "f"(e0));
    return r;
}

// cp.async helpers (16B)
__device__ __forceinline__ void cp16(void* smem_dst, const void* gsrc) {
    uint32_t d = (uint32_t)__cvta_generic_to_shared(smem_dst);
    asm volatile("cp.async.ca.shared.global [%0], [%1], 16;" :: "r"(d), "l"(gsrc) : "memory");
}
#define CP_COMMIT() asm volatile("cp.async.commit_group;" ::: "memory")
#define CP_WAIT0()  asm volatile("cp.async.wait_group 0;" ::: "memory")

// ---------------- small kernels ----------------
__global__ void embed_kernel(const float* __restrict__ h0,
                             const float* __restrict__ emb_w,
                             const float* __restrict__ emb_b) {
    int idx = blockIdx.x * 256 + threadIdx.x;
    if (idx >= NN * HID) return;
    int n = idx >> 7, j = idx & 127;
    float acc = emb_b[j];
#pragma unroll
    for (int k = 0; k < IN_NODE; k++)
        acc += h0[n * IN_NODE + k] * emb_w[k * HID + j];
    g_h0buf[idx] = acc;
}

__global__ void zero_agg_kernel() {
    int i = blockIdx.x * 256 + threadIdx.x;
    if (i < NN * HID / 4)
        ((float4*)g_agg)[i] = make_float4(0.f, 0.f, 0.f, 0.f);
}

// fp16 weight prep: edge W2 [K][N] + ew1 rows 0..255
__global__ void wf16prep_kernel(const float* __restrict__ ew2,
                                const float* __restrict__ ew1) {
    int idx = blockIdx.x * 256 + threadIdx.x;
    if (idx >= 98304) return;
    if (idx < 32768) {
        int layer = idx >> 14, rem = idx & 16383;
        g_Wf16[layer][rem] = __float2half(ew2[layer * HID * HID + rem]);
    } else {
        int t = idx - 32768;
        int l = t >> 15, rest = t & 32767;
        int y = rest >> 14, r2 = rest & 16383;
        g_E1f16[l][y][r2] =
            __float2half(ew1[(l * 261 + y * 128 + (r2 >> 7)) * 128 + (r2 & 127)]);
    }
}

// split node W1 (wsum-folded) and node W2 into bf16 hi/lo
__global__ void prep_split_kernel(const float* __restrict__ nw1,
                                  const float* __restrict__ nw2) {
    int idx = blockIdx.x * 256 + threadIdx.x;
    if (idx >= 98304) return;
    float v;
    __nv_bfloat16 *dh, *dl;
    if (idx < 65536) {
        int l = idx >> 15, rest = idx & 32767;
        int k = rest >> 7, j = rest & 127;
        if (k < 128)
            v = nw1[(l * 384 + k) * 128 + j] + nw1[(l * 384 + 256 + k) * 128 + j];
        else
            v = nw1[(l * 384 + 128 + (k - 128)) * 128 + j];
        dh = &g_N1h[l][rest];
        dl = &g_N1l[l][rest];
    } else {
        int t = idx - 65536;
        int l = t >> 14, rest = t & 16383;
        v = nw2[l * 16384 + rest];
        dh = &g_N2h[l][rest];
        dl = &g_N2l[l][rest];
    }
    __nv_bfloat16 hb = __float2bfloat16(v);
    *dh = hb;
    *dl = __float2bfloat16(v - __bfloat162float(hb));
}

// ---------------- counting sort of edges by row ----------------
__global__ void sort_zero_kernel() {
    int i = blockIdx.x * 256 + threadIdx.x;
    if (i < NN) g_cnt[i] = 0;
}

__global__ void sort_hist_kernel(const int* __restrict__ row) {
    int e = blockIdx.x * 256 + threadIdx.x;
    if (e < NE) atomicAdd(&g_cnt[row[e]], 1);
}

__global__ void sort_scan1_kernel() {
    __shared__ int buf[512];
    int t = threadIdx.x;
    int i = blockIdx.x * 512 + t;
    int v = (i < NN) ? g_cnt[i] : 0;
    buf[t] = v;
    __syncthreads();
#pragma unroll
    for (int d = 1; d < 512; d <<= 1) {
        int x = (t >= d) ? buf[t - d] : 0;
        __syncthreads();
        buf[t] += x;
        __syncthreads();
    }
    g_off[i] = buf[t] - v;
    if (t == 511) g_blksum[blockIdx.x] = buf[511];
}

__global__ void sort_scan2_kernel() {
    if (threadIdx.x == 0) {
        int s = 0;
        for (int k = 0; k < NB_SCAN; k++) {
            g_blkoff[k] = s;
            s += g_blksum[k];
        }
    }
}

__global__ void sort_scan3_kernel() {
    int i = blockIdx.x * 256 + threadIdx.x;
    if (i < NN) {
        int o = g_off[i] + g_blkoff[i >> 9];
        g_off[i] = o;
        g_cur[i] = o;
    }
}

__global__ void sort_scatter_kernel(const int* __restrict__ row,
                                    const int* __restrict__ col,
                                    const float* __restrict__ x,
                                    const float* __restrict__ edge_attr) {
    int e = blockIdx.x * 256 + threadIdx.x;
    if (e >= NE) return;
    int r = row[e], c = col[e];
    float dx = x[r * 3 + 0] - x[c * 3 + 0];
    float dy = x[r * 3 + 1] - x[c * 3 + 1];
    float dz = x[r * 3 + 2] - x[c * 3 + 2];
    float rad = dx * dx + dy * dy + dz * dz;
    int pos = atomicAdd(&g_cur[r], 1);
    g_rowS[pos] = r;
    g_colS[pos] = c;
    g_radS[pos] = rad;
    g_eaS[pos] = *(const float4*)(edge_attr + (size_t)e * 4);
}

// ---------------- pre kernel: single-pass fp16 GEMM, P = h @ E1 (fp16 out) ----------------
static constexpr int PF_ST = 136;   // fp16 stride
static constexpr int PF_DST = 132;  // f32 stride, D (unions A+B)
static constexpr int PRE_SMEM = 69632;  // A 34816 + B 34816; D 67584 unions at 0

__global__ void __launch_bounds__(256, 2)
pre_f16_kernel(const float* __restrict__ hsrc,
               const __half* __restrict__ B1, __half* __restrict__ P1,
               const __half* __restrict__ B2, __half* __restrict__ P2) {
    extern __shared__ char smem[];
    __half* sA = (__half*)smem;
    __half* sB = (__half*)(smem + 34816);
    float* sD  = (float*)smem;

    const __half* B = (blockIdx.y == 0) ? B1 : B2;
    __half* P = (blockIdx.y == 0) ? P1 : P2;

    int tid = threadIdx.x;
    int wid = tid >> 5;
    int n0 = blockIdx.x * 128;
    int r = tid >> 1, hf = tid & 1;
    int n = n0 + r;

    // prefetch full B [128][128] fp16
    {
#pragma unroll
        for (int it = 0; it < 8; it++) {
            int i = tid + it * 256;
            int k = i >> 4, u = i & 15;
            cp16(sB + k * PF_ST + u * 8, B + (size_t)k * HID + u * 8);
        }
        CP_COMMIT();
    }

    // stage A: fp32 h -> fp16
    if (n < NN) {
#pragma unroll
        for (int q = 0; q < 16; q++) {
            int col = hf * 64 + q * 4;
            float4 v = *(const float4*)(hsrc + (size_t)n * HID + col);
            __half2* pa = (__half2*)(sA + r * PF_ST + col);
            pa[0] = __floats2half2_rn(v.x, v.y);
            pa[1] = __floats2half2_rn(v.z, v.w);
        }
    } else {
#pragma unroll
        for (int q = 0; q < 16; q++) {
            int col = hf * 64 + q * 4;
            __half2* pa = (__half2*)(sA + r * PF_ST + col);
            pa[0] = __half2half2(__float2half(0.f));
            pa[1] = __half2half2(__float2half(0.f));
        }
    }
    CP_WAIT0();
    __syncthreads();

    using namespace nvcuda::wmma;
    {
        int m0 = wid * 16;
        fragment<accumulator, 16, 16, 16, float> acc[8];
#pragma unroll
        for (int j = 0; j < 8; j++) fill_fragment(acc[j], 0.f);
#pragma unroll
        for (int k = 0; k < 8; k++) {
            fragment<matrix_a, 16, 16, 16, __half, row_major> a;
            load_matrix_sync(a, sA + m0 * PF_ST + k * 16, PF_ST);
#pragma unroll
            for (int nf = 0; nf < 8; nf++) {
                fragment<matrix_b, 16, 16, 16, __half, row_major> b;
                load_matrix_sync(b, sB + (k * 16) * PF_ST + nf * 16, PF_ST);
                mma_sync(acc[nf], a, b, acc[nf]);
            }
        }
        __syncthreads();
#pragma unroll
        for (int nf = 0; nf < 8; nf++)
            store_matrix_sync(sD + m0 * PF_DST + nf * 16, acc[nf], PF_DST, mem_row_major);
    }
    __syncthreads();

    if (n < NN) {
#pragma unroll
        for (int q = 0; q < 16; q++) {
            int col = hf * 64 + q * 4;
            float4 v = *(const float4*)(sD + r * PF_DST + col);
            __half2* po = (__half2*)(P + (size_t)n * HID + col);
            po[0] = __floats2half2_rn(v.x, v.y);
            po[1] = __floats2half2_rn(v.z, v.w);
        }
    }
}

// ---------------- generic dense GEMM (bf16 3-pass, cp.async): node GEMMs ----------------
static constexpr int GA_ST = 72;
static constexpr int GB_ST = 136;
static constexpr int GD_ST = 132;
static constexpr int G_SAH = 0;
static constexpr int G_SAL = 18432;
static constexpr int G_SBH = 36864;
static constexpr int G_SBL = 54272;
static constexpr int GEMM_SMEM = 71680;

__global__ void __launch_bounds__(256, 2)
gemm_wmma_kernel(const float* __restrict__ A0, const float* __restrict__ A1,
                 int k64,
                 const __nv_bfloat16* __restrict__ Bh,
                 const __nv_bfloat16* __restrict__ Bl,
                 const float* __restrict__ bias,
                 float* __restrict__ out, int do_elu) {
    extern __shared__ char smem[];
    __nv_bfloat16* sAh = (__nv_bfloat16*)(smem + G_SAH);
    __nv_bfloat16* sAl = (__nv_bfloat16*)(smem + G_SAL);
    __nv_bfloat16* sBh = (__nv_bfloat16*)(smem + G_SBH);
    __nv_bfloat16* sBl = (__nv_bfloat16*)(smem + G_SBL);
    float* sD = (float*)smem;

    int tid = threadIdx.x;
    int wid = tid >> 5;
    int n0 = blockIdx.x * 128;
    int r = tid >> 1, hf = tid & 1;
    int n = n0 + r;

    using namespace nvcuda::wmma;
    fragment<accumulator, 16, 16, 16, float> acc[8];
#pragma unroll
    for (int j = 0; j < 8; j++) fill_fragment(acc[j], 0.f);

    for (int c = 0; c < k64; c++) {
        {
#pragma unroll
            for (int it = 0; it < 4; it++) {
                int i = tid + it * 256;
                int kb = i >> 4, u = i & 15;
                cp16(sBh + kb * GB_ST + u * 8, Bh + (size_t)(c * 64 + kb) * HID + u * 8);
                cp16(sBl + kb * GB_ST + u * 8, Bl + (size_t)(c * 64 + kb) * HID + u * 8);
            }
            CP_COMMIT();
        }
        {
            const float* src = (c < 2) ? A0 : A1;
            int kbase = (c & 1) * 64;
            if (n < NN) {
#pragma unroll
                for (int q = 0; q < 8; q++) {
                    int col = hf * 32 + q * 4;
                    float4 v = *(const float4*)(src + (size_t)n * HID + kbase + col);
                    float h0f = __bfloat162float(__float2bfloat16(v.x));
                    float h1f = __bfloat162float(__float2bfloat16(v.y));
                    float h2f = __bfloat162float(__float2bfloat16(v.z));
                    float h3f = __bfloat162float(__float2bfloat16(v.w));
                    uint32_t* ph = (uint32_t*)(sAh + r * GA_ST + col);
                    uint32_t* pl = (uint32_t*)(sAl + r * GA_ST + col);
                    ph[0] = pack_bf16(h0f, h1f);
                    ph[1] = pack_bf16(h2f, h3f);
                    pl[0] = pack_bf16(v.x - h0f, v.y - h1f);
                    pl[1] = pack_bf16(v.z - h2f, v.w - h3f);
                }
            } else {
#pragma unroll
                for (int q = 0; q < 8; q++) {
                    int col = hf * 32 + q * 4;
                    uint32_t* ph = (uint32_t*)(sAh + r * GA_ST + col);
                    uint32_t* pl = (uint32_t*)(sAl + r * GA_ST + col);
                    ph[0] = 0; ph[1] = 0; pl[0] = 0; pl[1] = 0;
                }
            }
        }
        CP_WAIT0();
        __syncthreads();

        {
            int m0 = wid * 16;
#pragma unroll
            for (int kf = 0; kf < 4; kf++) {
                fragment<matrix_a, 16, 16, 16, __nv_bfloat16, row_major> ah, al;
                load_matrix_sync(ah, sAh + m0 * GA_ST + kf * 16, GA_ST);
                load_matrix_sync(al, sAl + m0 * GA_ST + kf * 16, GA_ST);
#pragma unroll
                for (int nf = 0; nf < 8; nf++) {
                    fragment<matrix_b, 16, 16, 16, __nv_bfloat16, row_major> b;
                    load_matrix_sync(b, sBh + (kf * 16) * GB_ST + nf * 16, GB_ST);
                    mma_sync(acc[nf], ah, b, acc[nf]);
                    mma_sync(acc[nf], al, b, acc[nf]);
                }
            }
#pragma unroll
            for (int kf = 0; kf < 4; kf++) {
                fragment<matrix_a, 16, 16, 16, __nv_bfloat16, row_major> ah;
                load_matrix_sync(ah, sAh + m0 * GA_ST + kf * 16, GA_ST);
#pragma unroll
                for (int nf = 0; nf < 8; nf++) {
                    fragment<matrix_b, 16, 16, 16, __nv_bfloat16, row_major> b;
                    load_matrix_sync(b, sBl + (kf * 16) * GB_ST + nf * 16, GB_ST);
                    mma_sync(acc[nf], ah, b, acc[nf]);
                }
            }
        }
        __syncthreads();
    }

    {
        int m0 = wid * 16;
#pragma unroll
        for (int nf = 0; nf < 8; nf++)
            store_matrix_sync(sD + m0 * GD_ST + nf * 16, acc[nf], GD_ST, mem_row_major);
    }
    __syncthreads();

    if (n < NN) {
#pragma unroll
        for (int q = 0; q < 16; q++) {
            int col = hf * 64 + q * 4;
            float4 v = *(const float4*)(sD + r * GD_ST + col);
            if (bias) {
                v.x += bias[col + 0];
                v.y += bias[col + 1];
                v.z += bias[col + 2];
                v.w += bias[col + 3];
            }
            if (do_elu) {
                v.x = elu(v.x); v.y = elu(v.y); v.z = elu(v.z); v.w = elu(v.w);
            }
            *(float4*)(out + (size_t)n * HID + col) = v;
        }
    }
}

// ---------------- edge kernel: single-pass fp16 MMA, WIDE fp16 P gather ----------------
static constexpr int AST = 136;   // fp16 stride
static constexpr int DSTR = 132;  // f32 stride, D (unions A+B after MMA)
static constexpr int SM_A  = 0;        // 128*136*2 = 34816
static constexpr int SM_B  = 34816;    // 34816 -> 69632
static constexpr int SM_WT = 69632;    // 5*128*4 = 2560
static constexpr int SM_B1 = 72192;    // 512
static constexpr int SM_B2 = 72704;    // 512
static constexpr int SM_ROW = 73216;   // 512
static constexpr int EDGE_SMEM_BYTES = 73728;

__global__ void __launch_bounds__(256, 2)
edge_hmma_kernel(const float* __restrict__ ew1, const float* __restrict__ eb1,
                 const float* __restrict__ eb2, int layer) {
    extern __shared__ char smem[];
    __half* sA = (__half*)(smem + SM_A);
    __half* sB = (__half*)(smem + SM_B);
    float* sD  = (float*)smem;
    float* sWT = (float*)(smem + SM_WT);
    float* sB1 = (float*)(smem + SM_B1);
    float* sB2 = (float*)(smem + SM_B2);
    int*   sRow = (int*)(smem + SM_ROW);

    int tid = threadIdx.x;
    int wid = tid >> 5;
    int e0 = blockIdx.x * 128;

    // prefetch full B [128k][128n] fp16 via cp.async (hides behind A-build)
    {
        const __half* gW = g_Wf16[layer];
#pragma unroll
        for (int it = 0; it < 8; it++) {
            int i = tid + it * 256;
            int k = i >> 4, u = i & 15;
            cp16(sB + k * AST + u * 8, gW + k * HID + u * 8);
        }
        CP_COMMIT();
    }

    // stage tail weights, biases, sorted rows
    for (int i = tid; i < 5 * HID; i += 256) sWT[i] = ew1[(layer * 261 + 2 * HID) * HID + i];
    if (tid < HID) {
        sB1[tid] = eb1[layer * HID + tid];
        sB2[tid] = eb2[layer * HID + tid];
    }
    if (tid < 128) sRow[tid] = g_rowS[e0 + tid];
    __syncthreads();

    // A-build: elu(P1[row]+P2[col]+rad*w+ea@Wtail+b1) -> fp16
    // fp16 P gathered with 16B uint4 loads (8 halves per load)
    {
        int m = tid >> 1, hf = tid & 1;
        int e = e0 + m;
        int r = sRow[m], c = g_colS[e];
        float rad = g_radS[e];
        float4 ea = g_eaS[e];
        const __half* p1r = g_P1h + (size_t)r * HID;
        const __half* p2r = g_P2h + (size_t)c * HID;
#pragma unroll
        for (int q = 0; q < 8; q++) {
            int jb = hf * 64 + q * 8;
            uint4 u1 = *(const uint4*)(p1r + jb);   // 8 halves
            uint4 u2 = *(const uint4*)(p2r + jb);
            const __half2* h1 = (const __half2*)&u1;
            const __half2* h2 = (const __half2*)&u2;
            __half2* pa = (__half2*)(sA + m * AST + jb);
#pragma unroll
            for (int s = 0; s < 2; s++) {           // two 4-col sub-steps
                int j4 = jb + s * 4;
                float2 p1a = __half22float2(h1[s * 2 + 0]);
                float2 p1b = __half22float2(h1[s * 2 + 1]);
                float2 p2a = __half22float2(h2[s * 2 + 0]);
                float2 p2b = __half22float2(h2[s * 2 + 1]);
                float4 w0 = *(const float4*)(sWT + 0 * HID + j4);
                float4 w1 = *(const float4*)(sWT + 1 * HID + j4);
                float4 w2 = *(const float4*)(sWT + 2 * HID + j4);
                float4 w3 = *(const float4*)(sWT + 3 * HID + j4);
                float4 w4 = *(const float4*)(sWT + 4 * HID + j4);
                float4 bb = *(const float4*)(sB1 + j4);
                float o0 = elu(p1a.x + p2a.x + rad * w0.x + ea.x * w1.x + ea.y * w2.x + ea.z * w3.x + ea.w * w4.x + bb.x);
                float o1 = elu(p1a.y + p2a.y + rad * w0.y + ea.x * w1.y + ea.y * w2.y + ea.z * w3.y + ea.w * w4.y + bb.y);
                float o2 = elu(p1b.x + p2b.x + rad * w0.z + ea.x * w1.z + ea.y * w2.z + ea.z * w3.z + ea.w * w4.z + bb.z);
                float o3 = elu(p1b.y + p2b.y + rad * w0.w + ea.x * w1.w + ea.y * w2.w + ea.z * w3.w + ea.w * w4.w + bb.w);
                pa[s * 2 + 0] = __floats2half2_rn(o0, o1);
                pa[s * 2 + 1] = __floats2half2_rn(o2, o3);
            }
        }
    }
    CP_WAIT0();
    __syncthreads();

    // single-pass fp16 MMA: warp wid -> rows [wid*16,+16), all 128 cols
    using namespace nvcuda::wmma;
    {
        int m0 = wid * 16;
        fragment<accumulator, 16, 16, 16, float> acc[8];
#pragma unroll
        for (int j = 0; j < 8; j++) fill_fragment(acc[j], 0.f);

#pragma unroll
        for (int k = 0; k < 8; k++) {
            fragment<matrix_a, 16, 16, 16, __half, row_major> a;
            load_matrix_sync(a, sA + m0 * AST + k * 16, AST);
#pragma unroll
            for (int nf = 0; nf < 8; nf++) {
                fragment<matrix_b, 16, 16, 16, __half, row_major> b;
                load_matrix_sync(b, sB + (k * 16) * AST + nf * 16, AST);
                mma_sync(acc[nf], a, b, acc[nf]);
            }
        }

        __syncthreads();   // A and B fully dead -> D may overwrite
#pragma unroll
        for (int nf = 0; nf < 8; nf++)
            store_matrix_sync(sD + m0 * DSTR + nf * 16, acc[nf], DSTR, mem_row_major);
    }
    __syncthreads();

    // single merged scatter: eg = 8-edge group, ct = 8-col group
    {
        int ct = tid & 15, eg = tid >> 4;
        int jb = ct * 8;
        float b2v[8];
#pragma unroll
        for (int k = 0; k < 8; k++) b2v[k] = sB2[jb + k];
        float run[8];
#pragma unroll
        for (int k = 0; k < 8; k++) run[k] = 0.f;
        int cur = sRow[eg * 8];
#pragma unroll
        for (int i = 0; i < 8; i++) {
            int m = eg * 8 + i;
            int rr = sRow[m];
            if (rr != cur) {
                float* dst = g_agg + (size_t)cur * HID + jb;
                red4(dst, run[0], run[1], run[2], run[3]);
                red4(dst + 4, run[4], run[5], run[6], run[7]);
#pragma unroll
                for (int k = 0; k < 8; k++) run[k] = 0.f;
                cur = rr;
            }
            const float* sd = sD + m * DSTR + jb;
#pragma unroll
            for (int k = 0; k < 8; k++) run[k] += elu(sd[k] + b2v[k]);
        }
        float* dst = g_agg + (size_t)cur * HID + jb;
        red4(dst, run[0], run[1], run[2], run[3]);
        red4(dst + 4, run[4], run[5], run[6], run[7]);
    }
}

// ---------------- final head ----------------
__global__ void final_kernel(const float* __restrict__ label,
                             const float* __restrict__ eps,
                             const float* __restrict__ mu_w, const float* __restrict__ mu_b,
                             const float* __restrict__ var_w, const float* __restrict__ var_b,
                             float* __restrict__ out) {
    int idx = blockIdx.x * 256 + threadIdx.x;
    if (idx >= NN * LATD) return;
    int n = idx >> 6, l = idx & 63;
    float am = mu_b[l], av = var_b[l];
    const float* hrow = g_h0buf + n * HID;
#pragma unroll 4
    for (int k = 0; k < HID; k++) {
        float hv = hrow[k];
        am += hv * mu_w[k * LATD + l];
        av += hv * var_w[k * LATD + l];
    }
#pragma unroll
    for (int c = 0; c < 7; c++) {
        float lv = label[n * 7 + c];
        am += lv * mu_w[(HID + c) * LATD + l];
        av += lv * var_w[(HID + c) * LATD + l];
    }
    out[idx] = am + 0.01f * eps[idx] * __expf(0.5f * av);
}

// ---------------- launch ----------------
extern "C" void kernel_launch(void* const* d_in, const int* in_sizes, int n_in,
                              void* d_out, int out_size) {
    const float* h0        = (const float*)d_in[0];
    const float* label     = (const float*)d_in[1];
    const float* x         = (const float*)d_in[2];
    const float* edge_attr = (const float*)d_in[3];
    const float* eps       = (const float*)d_in[4];
    const float* emb_w     = (const float*)d_in[5];
    const float* emb_b     = (const float*)d_in[6];
    const float* ew1       = (const float*)d_in[7];
    const float* eb1       = (const float*)d_in[8];
    const float* ew2       = (const float*)d_in[9];
    const float* eb2       = (const float*)d_in[10];
    const float* nw1       = (const float*)d_in[11];
    const float* nb1       = (const float*)d_in[12];
    const float* nw2       = (const float*)d_in[13];
    const float* nb2       = (const float*)d_in[14];
    const float* mu_w      = (const float*)d_in[15];
    const float* mu_b      = (const float*)d_in[16];
    const float* var_w     = (const float*)d_in[17];
    const float* var_b     = (const float*)d_in[18];
    const int*   edges     = (const int*)d_in[19];
    const int* rowp = edges;
    const int* colp = edges + NE;
    float* out = (float*)d_out;

    cudaFuncSetAttribute(edge_hmma_kernel, cudaFuncAttributeMaxDynamicSharedMemorySize, EDGE_SMEM_BYTES);
    cudaFuncSetAttribute(gemm_wmma_kernel, cudaFuncAttributeMaxDynamicSharedMemorySize, GEMM_SMEM);
    cudaFuncSetAttribute(pre_f16_kernel, cudaFuncAttributeMaxDynamicSharedMemorySize, PRE_SMEM);

    const int GGRID = (NN + 127) / 128;   // 391

    embed_kernel<<<(NN * HID + 255) / 256, 256>>>(h0, emb_w, emb_b);
    wf16prep_kernel<<<(98304 + 255) / 256, 256>>>(ew2, ew1);
    prep_split_kernel<<<(98304 + 255) / 256, 256>>>(nw1, nw2);

    // counting sort of edges by source node (once per launch)
    sort_zero_kernel<<<(NN + 255) / 256, 256>>>();
    sort_hist_kernel<<<(NE + 255) / 256, 256>>>(rowp);
    sort_scan1_kernel<<<NB_SCAN, 512>>>();
    sort_scan2_kernel<<<1, 32>>>();
    sort_scan3_kernel<<<(NN + 255) / 256, 256>>>();
    sort_scatter_kernel<<<(NE + 255) / 256, 256>>>(rowp, colp, x, edge_attr);

    float *h0p, *h1p, *aggp, *nfp;
    cudaGetSymbolAddress((void**)&h0p, g_h0buf);
    cudaGetSymbolAddress((void**)&h1p, g_h1buf);
    cudaGetSymbolAddress((void**)&aggp, g_agg);
    cudaGetSymbolAddress((void**)&nfp, g_nf);
    __half *p1p, *p2p, *e1f;
    cudaGetSymbolAddress((void**)&p1p, g_P1h);
    cudaGetSymbolAddress((void**)&p2p, g_P2h);
    cudaGetSymbolAddress((void**)&e1f, g_E1f16);
    __nv_bfloat16 *n1h, *n1l, *n2h, *n2l;
    cudaGetSymbolAddress((void**)&n1h, g_N1h);
    cudaGetSymbolAddress((void**)&n1l, g_N1l);
    cudaGetSymbolAddress((void**)&n2h, g_N2h);
    cudaGetSymbolAddress((void**)&n2l, g_N2l);

    for (int layer = 0; layer < 2; layer++) {
        float* hsrc_p = (layer == 0) ? h0p : h1p;
        float* hdst   = (layer == 0) ? h1p : h0p;

        zero_agg_kernel<<<(NN * HID / 4 + 255) / 256, 256>>>();

        // P1 and P2 in one launch (single-pass fp16, fp16 out)
        pre_f16_kernel<<<dim3(GGRID, 2), 256, PRE_SMEM>>>(
            hsrc_p,
            e1f + (size_t)layer * 2 * HID * HID, p1p,
            e1f + ((size_t)layer * 2 + 1) * HID * HID, p2p);

        edge_hmma_kernel<<<NE / 128, 256, EDGE_SMEM_BYTES>>>(ew1, eb1, eb2, layer);

        // node GEMM1: nf = elu([h|agg] @ N1 + nb1)
        gemm_wmma_kernel<<<GGRID, 256, GEMM_SMEM>>>(
            hsrc_p, aggp, 4,
            n1h + (size_t)layer * 2 * HID * HID, n1l + (size_t)layer * 2 * HID * HID,
            nb1 + layer * HID, nfp, 1);
        // node GEMM2: hdst = nf @ N2 + nb2
        gemm_wmma_kernel<<<GGRID, 256, GEMM_SMEM>>>(
            nfp, nullptr, 2,
            n2h + (size_t)layer * HID * HID, n2l + (size_t)layer * HID * HID,
            nb2 + layer * HID, hdst, 0);
    }

    final_kernel<<<(NN * LATD + 255) / 256, 256>>>(label, eps, mu_w, mu_b,
                                                   var_w, var_b, out);
}

// round 14
// speedup vs baseline: 1.3696x; 1.1147x over previous
#include <cuda_runtime.h>
#include <cuda_bf16.h>
#include <cuda_fp16.h>
#include <mma.h>
#include <cstdint>

#define NN 50000
#define NE 800000
#define HID 128
#define LATD 64
#define IN_NODE 11
#define IN_EDGE 4
#define NB_SCAN 98   // ceil(50000/512)

// ---------------- device scratch ----------------
__device__ float g_h0buf[NN * HID];
__device__ float g_h1buf[NN * HID];
__device__ float g_agg[NN * HID];
__device__ __half g_P1h[NN * HID];
__device__ __half g_P2h[NN * HID];
// counting-sort scratch
__device__ int g_cnt[NN];
__device__ int g_off[NB_SCAN * 512];
__device__ int g_cur[NN];
__device__ int g_blksum[NB_SCAN];
__device__ int g_blkoff[NB_SCAN];
// permuted (row-sorted) edge arrays
__device__ int   g_rowS[NE];
__device__ int   g_colS[NE];
__device__ float g_radS[NE];
__device__ float4 g_eaS[NE];
// fp16 weights
__device__ __half g_Wf16[2][HID * HID];          // edge W2 [K][N]
__device__ __half g_E1f16[2][2][HID * HID];      // ew1 rows 0..255
__device__ __half g_N1f16[2][2 * HID * HID];     // node [wsum ; W1b] [256][128]
__device__ __half g_N2f16[2][HID * HID];         // node W2 [128][128]

__device__ __forceinline__ float elu(float v) {
    return v > 0.f ? v : (__expf(v) - 1.f);
}

__device__ __forceinline__ void red4(float* p, float a, float b, float c, float d) {
    asm volatile("red.global.add.v4.f32 [%0], {%1,%2,%3,%4};"
                 :: "l"(p), "f"(a), "f"(b), "f"(c), "f"(d) : "memory");
}

// cp.async helpers (16B)
__device__ __forceinline__ void cp16(void* smem_dst, const void* gsrc) {
    uint32_t d = (uint32_t)__cvta_generic_to_shared(smem_dst);
    asm volatile("cp.async.ca.shared.global [%0], [%1], 16;" :: "r"(d), "l"(gsrc) : "memory");
}
#define CP_COMMIT() asm volatile("cp.async.commit_group;" ::: "memory")
#define CP_WAIT0()  asm volatile("cp.async.wait_group 0;" ::: "memory")

// ---------------- small kernels ----------------
__global__ void embed_kernel(const float* __restrict__ h0,
                             const float* __restrict__ emb_w,
                             const float* __restrict__ emb_b) {
    int idx = blockIdx.x * 256 + threadIdx.x;
    if (idx >= NN * HID) return;
    int n = idx >> 7, j = idx & 127;
    float acc = emb_b[j];
#pragma unroll
    for (int k = 0; k < IN_NODE; k++)
        acc += h0[n * IN_NODE + k] * emb_w[k * HID + j];
    g_h0buf[idx] = acc;
}

__global__ void zero_agg_kernel() {
    int i = blockIdx.x * 256 + threadIdx.x;
    if (i < NN * HID / 4)
        ((float4*)g_agg)[i] = make_float4(0.f, 0.f, 0.f, 0.f);
}

// fp16 weight prep: edge W2, ew1 rows 0..255, node N1 (wsum-folded), node N2
__global__ void wf16prep_kernel(const float* __restrict__ ew2,
                                const float* __restrict__ ew1,
                                const float* __restrict__ nw1,
                                const float* __restrict__ nw2) {
    int idx = blockIdx.x * 256 + threadIdx.x;
    if (idx >= 196608) return;
    if (idx < 32768) {
        int layer = idx >> 14, rem = idx & 16383;
        g_Wf16[layer][rem] = __float2half(ew2[layer * HID * HID + rem]);
    } else if (idx < 98304) {
        int t = idx - 32768;
        int l = t >> 15, rest = t & 32767;
        int y = rest >> 14, r2 = rest & 16383;
        g_E1f16[l][y][r2] =
            __float2half(ew1[(l * 261 + y * 128 + (r2 >> 7)) * 128 + (r2 & 127)]);
    } else if (idx < 163840) {
        int t = idx - 98304;
        int l = t >> 15, rest = t & 32767;
        int k = rest >> 7, j = rest & 127;
        float v;
        if (k < 128)
            v = nw1[(l * 384 + k) * 128 + j] + nw1[(l * 384 + 256 + k) * 128 + j];
        else
            v = nw1[(l * 384 + 128 + (k - 128)) * 128 + j];
        g_N1f16[l][rest] = __float2half(v);
    } else {
        int t = idx - 163840;
        int l = t >> 14, rest = t & 16383;
        g_N2f16[l][rest] = __float2half(nw2[l * 16384 + rest]);
    }
}

// ---------------- counting sort of edges by row ----------------
__global__ void sort_zero_kernel() {
    int i = blockIdx.x * 256 + threadIdx.x;
    if (i < NN) g_cnt[i] = 0;
}

__global__ void sort_hist_kernel(const int* __restrict__ row) {
    int e = blockIdx.x * 256 + threadIdx.x;
    if (e < NE) atomicAdd(&g_cnt[row[e]], 1);
}

__global__ void sort_scan1_kernel() {
    __shared__ int buf[512];
    int t = threadIdx.x;
    int i = blockIdx.x * 512 + t;
    int v = (i < NN) ? g_cnt[i] : 0;
    buf[t] = v;
    __syncthreads();
#pragma unroll
    for (int d = 1; d < 512; d <<= 1) {
        int x = (t >= d) ? buf[t - d] : 0;
        __syncthreads();
        buf[t] += x;
        __syncthreads();
    }
    g_off[i] = buf[t] - v;
    if (t == 511) g_blksum[blockIdx.x] = buf[511];
}

__global__ void sort_scan2_kernel() {
    if (threadIdx.x == 0) {
        int s = 0;
        for (int k = 0; k < NB_SCAN; k++) {
            g_blkoff[k] = s;
            s += g_blksum[k];
        }
    }
}

__global__ void sort_scan3_kernel() {
    int i = blockIdx.x * 256 + threadIdx.x;
    if (i < NN) {
        int o = g_off[i] + g_blkoff[i >> 9];
        g_off[i] = o;
        g_cur[i] = o;
    }
}

__global__ void sort_scatter_kernel(const int* __restrict__ row,
                                    const int* __restrict__ col,
                                    const float* __restrict__ x,
                                    const float* __restrict__ edge_attr) {
    int e = blockIdx.x * 256 + threadIdx.x;
    if (e >= NE) return;
    int r = row[e], c = col[e];
    float dx = x[r * 3 + 0] - x[c * 3 + 0];
    float dy = x[r * 3 + 1] - x[c * 3 + 1];
    float dz = x[r * 3 + 2] - x[c * 3 + 2];
    float rad = dx * dx + dy * dy + dz * dz;
    int pos = atomicAdd(&g_cur[r], 1);
    g_rowS[pos] = r;
    g_colS[pos] = c;
    g_radS[pos] = rad;
    g_eaS[pos] = *(const float4*)(edge_attr + (size_t)e * 4);
}

// ---------------- pre kernel: single-pass fp16 GEMM, P = h @ E1 (fp16 out) ----------------
static constexpr int PF_ST = 136;
static constexpr int PF_DST = 132;
static constexpr int PRE_SMEM = 69632;

__global__ void __launch_bounds__(256, 2)
pre_f16_kernel(const float* __restrict__ hsrc,
               const __half* __restrict__ B1, __half* __restrict__ P1,
               const __half* __restrict__ B2, __half* __restrict__ P2) {
    extern __shared__ char smem[];
    __half* sA = (__half*)smem;
    __half* sB = (__half*)(smem + 34816);
    float* sD  = (float*)smem;

    const __half* B = (blockIdx.y == 0) ? B1 : B2;
    __half* P = (blockIdx.y == 0) ? P1 : P2;

    int tid = threadIdx.x;
    int wid = tid >> 5;
    int n0 = blockIdx.x * 128;
    int r = tid >> 1, hf = tid & 1;
    int n = n0 + r;

    {
#pragma unroll
        for (int it = 0; it < 8; it++) {
            int i = tid + it * 256;
            int k = i >> 4, u = i & 15;
            cp16(sB + k * PF_ST + u * 8, B + (size_t)k * HID + u * 8);
        }
        CP_COMMIT();
    }

    if (n < NN) {
#pragma unroll
        for (int q = 0; q < 16; q++) {
            int col = hf * 64 + q * 4;
            float4 v = *(const float4*)(hsrc + (size_t)n * HID + col);
            __half2* pa = (__half2*)(sA + r * PF_ST + col);
            pa[0] = __floats2half2_rn(v.x, v.y);
            pa[1] = __floats2half2_rn(v.z, v.w);
        }
    } else {
#pragma unroll
        for (int q = 0; q < 16; q++) {
            int col = hf * 64 + q * 4;
            __half2* pa = (__half2*)(sA + r * PF_ST + col);
            pa[0] = __half2half2(__float2half(0.f));
            pa[1] = __half2half2(__float2half(0.f));
        }
    }
    CP_WAIT0();
    __syncthreads();

    using namespace nvcuda::wmma;
    {
        int m0 = wid * 16;
        fragment<accumulator, 16, 16, 16, float> acc[8];
#pragma unroll
        for (int j = 0; j < 8; j++) fill_fragment(acc[j], 0.f);
#pragma unroll
        for (int k = 0; k < 8; k++) {
            fragment<matrix_a, 16, 16, 16, __half, row_major> a;
            load_matrix_sync(a, sA + m0 * PF_ST + k * 16, PF_ST);
#pragma unroll
            for (int nf = 0; nf < 8; nf++) {
                fragment<matrix_b, 16, 16, 16, __half, row_major> b;
                load_matrix_sync(b, sB + (k * 16) * PF_ST + nf * 16, PF_ST);
                mma_sync(acc[nf], a, b, acc[nf]);
            }
        }
        __syncthreads();
#pragma unroll
        for (int nf = 0; nf < 8; nf++)
            store_matrix_sync(sD + m0 * PF_DST + nf * 16, acc[nf], PF_DST, mem_row_major);
    }
    __syncthreads();

    if (n < NN) {
#pragma unroll
        for (int q = 0; q < 16; q++) {
            int col = hf * 64 + q * 4;
            float4 v = *(const float4*)(sD + r * PF_DST + col);
            __half2* po = (__half2*)(P + (size_t)n * HID + col);
            po[0] = __floats2half2_rn(v.x, v.y);
            po[1] = __floats2half2_rn(v.z, v.w);
        }
    }
}

// ---------------- fused node kernel: nf = elu([h|agg]@N1+b1); h' = nf@N2+b2 ----------------
static constexpr int NF_ST = 136;   // fp16 stride (A / nf / B)
static constexpr int ND_ST = 68;    // f32 stride for half-width D scratch
static constexpr int NR_A  = 0;         // 34816: A chunks, later nf fp16
static constexpr int NR_B  = 34816;     // 34816: B chunks (N1 halves, then N2)
static constexpr int NR_D  = 69632;     // 34816: half-D f32 scratch [128][68]
static constexpr int NR_B1 = 104448;    // 512
static constexpr int NR_B2 = 104960;    // 512
static constexpr int NODE_SMEM = 105472;

__global__ void __launch_bounds__(256, 2)
node_f16_kernel(const float* __restrict__ hsrc, const float* __restrict__ agg,
                const __half* __restrict__ N1, const __half* __restrict__ N2,
                const float* __restrict__ nb1, const float* __restrict__ nb2,
                float* __restrict__ hdst) {
    extern __shared__ char smem[];
    __half* sA  = (__half*)(smem + NR_A);
    __half* sB  = (__half*)(smem + NR_B);
    float*  sDh = (float*)(smem + NR_D);
    float*  sB1 = (float*)(smem + NR_B1);
    float*  sB2 = (float*)(smem + NR_B2);

    int tid = threadIdx.x;
    int wid = tid >> 5;
    int n0 = blockIdx.x * 128;
    int r = tid >> 1, hf = tid & 1;
    int n = n0 + r;
    int m0 = wid * 16;

    if (tid < HID) {
        sB1[tid] = nb1[tid];
        sB2[tid] = nb2[tid];
    }

    using namespace nvcuda::wmma;
    fragment<accumulator, 16, 16, 16, float> acc[8];
#pragma unroll
    for (int j = 0; j < 8; j++) fill_fragment(acc[j], 0.f);

    // GEMM1: K=256 in two 128-k chunks (chunk 0: h, chunk 1: agg)
#pragma unroll
    for (int c = 0; c < 2; c++) {
        {
#pragma unroll
            for (int it = 0; it < 8; it++) {
                int i = tid + it * 256;
                int k = i >> 4, u = i & 15;
                cp16(sB + k * NF_ST + u * 8, N1 + (size_t)(c * 128 + k) * HID + u * 8);
            }
            CP_COMMIT();
        }
        {
            const float* src = c ? agg : hsrc;
            if (n < NN) {
#pragma unroll
                for (int q = 0; q < 16; q++) {
                    int col = hf * 64 + q * 4;
                    float4 v = *(const float4*)(src + (size_t)n * HID + col);
                    __half2* pa = (__half2*)(sA + r * NF_ST + col);
                    pa[0] = __floats2half2_rn(v.x, v.y);
                    pa[1] = __floats2half2_rn(v.z, v.w);
                }
            } else {
#pragma unroll
                for (int q = 0; q < 16; q++) {
                    int col = hf * 64 + q * 4;
                    __half2* pa = (__half2*)(sA + r * NF_ST + col);
                    pa[0] = __half2half2(__float2half(0.f));
                    pa[1] = __half2half2(__float2half(0.f));
                }
            }
        }
        CP_WAIT0();
        __syncthreads();

#pragma unroll
        for (int k = 0; k < 8; k++) {
            fragment<matrix_a, 16, 16, 16, __half, row_major> a;
            load_matrix_sync(a, sA + m0 * NF_ST + k * 16, NF_ST);
#pragma unroll
            for (int nf = 0; nf < 8; nf++) {
                fragment<matrix_b, 16, 16, 16, __half, row_major> b;
                load_matrix_sync(b, sB + (k * 16) * NF_ST + nf * 16, NF_ST);
                mma_sync(acc[nf], a, b, acc[nf]);
            }
        }
        __syncthreads();   // A/B dead before restage (or nf conversion)
    }

    // prefetch N2 into sB (overlaps nf conversion; B region is dead now)
    {
#pragma unroll
        for (int it = 0; it < 8; it++) {
            int i = tid + it * 256;
            int k = i >> 4, u = i & 15;
            cp16(sB + k * NF_ST + u * 8, N2 + (size_t)k * HID + u * 8);
        }
        CP_COMMIT();
    }

    // nf = elu(D + b1) -> fp16 into sA, two 64-col halves via sDh scratch
#pragma unroll
    for (int half = 0; half < 2; half++) {
#pragma unroll
        for (int nt = 0; nt < 4; nt++)
            store_matrix_sync(sDh + m0 * ND_ST + nt * 16, acc[half * 4 + nt], ND_ST, mem_row_major);
        __syncthreads();
        {
#pragma unroll
            for (int q = 0; q < 8; q++) {
                int col4 = hf * 32 + q * 4;                 // within this half
                float4 v = *(const float4*)(sDh + r * ND_ST + col4);
                int gc = half * 64 + col4;
                float b0 = sB1[gc + 0], b1v = sB1[gc + 1], b2v = sB1[gc + 2], b3v = sB1[gc + 3];
                float o0 = elu(v.x + b0), o1 = elu(v.y + b1v);
                float o2 = elu(v.z + b2v), o3 = elu(v.w + b3v);
                __half2* pa = (__half2*)(sA + r * NF_ST + gc);
                pa[0] = __floats2half2_rn(o0, o1);
                pa[1] = __floats2half2_rn(o2, o3);
            }
        }
        __syncthreads();   // sDh dead before next half's store
    }
    CP_WAIT0();
    __syncthreads();

    // GEMM2: h' = nf @ N2 (K=128)
#pragma unroll
    for (int j = 0; j < 8; j++) fill_fragment(acc[j], 0.f);
#pragma unroll
    for (int k = 0; k < 8; k++) {
        fragment<matrix_a, 16, 16, 16, __half, row_major> a;
        load_matrix_sync(a, sA + m0 * NF_ST + k * 16, NF_ST);
#pragma unroll
        for (int nf = 0; nf < 8; nf++) {
            fragment<matrix_b, 16, 16, 16, __half, row_major> b;
            load_matrix_sync(b, sB + (k * 16) * NF_ST + nf * 16, NF_ST);
            mma_sync(acc[nf], a, b, acc[nf]);
        }
    }
    __syncthreads();   // sA/sB dead -> full-width D may overwrite [0, 67584)

    // full-width D (stride 132) over the A+B regions, then epilogue
    {
        float* sD = (float*)smem;
#pragma unroll
        for (int nf = 0; nf < 8; nf++)
            store_matrix_sync(sD + m0 * 132 + nf * 16, acc[nf], 132, mem_row_major);
        __syncthreads();
        if (n < NN) {
#pragma unroll
            for (int q = 0; q < 16; q++) {
                int col = hf * 64 + q * 4;
                float4 v = *(const float4*)(sD + r * 132 + col);
                v.x += sB2[col + 0];
                v.y += sB2[col + 1];
                v.z += sB2[col + 2];
                v.w += sB2[col + 3];
                *(float4*)(hdst + (size_t)n * HID + col) = v;
            }
        }
    }
}

// ---------------- edge kernel: single-pass fp16 MMA, wide fp16 P gather ----------------
static constexpr int AST = 136;
static constexpr int DSTR = 132;
static constexpr int SM_A  = 0;
static constexpr int SM_B  = 34816;
static constexpr int SM_WT = 69632;
static constexpr int SM_B1 = 72192;
static constexpr int SM_B2 = 72704;
static constexpr int SM_ROW = 73216;
static constexpr int EDGE_SMEM_BYTES = 73728;

__global__ void __launch_bounds__(256, 2)
edge_hmma_kernel(const float* __restrict__ ew1, const float* __restrict__ eb1,
                 const float* __restrict__ eb2, int layer) {
    extern __shared__ char smem[];
    __half* sA = (__half*)(smem + SM_A);
    __half* sB = (__half*)(smem + SM_B);
    float* sD  = (float*)smem;
    float* sWT = (float*)(smem + SM_WT);
    float* sB1 = (float*)(smem + SM_B1);
    float* sB2 = (float*)(smem + SM_B2);
    int*   sRow = (int*)(smem + SM_ROW);

    int tid = threadIdx.x;
    int wid = tid >> 5;
    int e0 = blockIdx.x * 128;

    {
        const __half* gW = g_Wf16[layer];
#pragma unroll
        for (int it = 0; it < 8; it++) {
            int i = tid + it * 256;
            int k = i >> 4, u = i & 15;
            cp16(sB + k * AST + u * 8, gW + k * HID + u * 8);
        }
        CP_COMMIT();
    }

    for (int i = tid; i < 5 * HID; i += 256) sWT[i] = ew1[(layer * 261 + 2 * HID) * HID + i];
    if (tid < HID) {
        sB1[tid] = eb1[layer * HID + tid];
        sB2[tid] = eb2[layer * HID + tid];
    }
    if (tid < 128) sRow[tid] = g_rowS[e0 + tid];
    __syncthreads();

    {
        int m = tid >> 1, hf = tid & 1;
        int e = e0 + m;
        int r = sRow[m], c = g_colS[e];
        float rad = g_radS[e];
        float4 ea = g_eaS[e];
        const __half* p1r = g_P1h + (size_t)r * HID;
        const __half* p2r = g_P2h + (size_t)c * HID;
#pragma unroll
        for (int q = 0; q < 8; q++) {
            int jb = hf * 64 + q * 8;
            uint4 u1 = *(const uint4*)(p1r + jb);
            uint4 u2 = *(const uint4*)(p2r + jb);
            const __half2* h1 = (const __half2*)&u1;
            const __half2* h2 = (const __half2*)&u2;
            __half2* pa = (__half2*)(sA + m * AST + jb);
#pragma unroll
            for (int s = 0; s < 2; s++) {
                int j4 = jb + s * 4;
                float2 p1a = __half22float2(h1[s * 2 + 0]);
                float2 p1b = __half22float2(h1[s * 2 + 1]);
                float2 p2a = __half22float2(h2[s * 2 + 0]);
                float2 p2b = __half22float2(h2[s * 2 + 1]);
                float4 w0 = *(const float4*)(sWT + 0 * HID + j4);
                float4 w1 = *(const float4*)(sWT + 1 * HID + j4);
                float4 w2 = *(const float4*)(sWT + 2 * HID + j4);
                float4 w3 = *(const float4*)(sWT + 3 * HID + j4);
                float4 w4 = *(const float4*)(sWT + 4 * HID + j4);
                float4 bb = *(const float4*)(sB1 + j4);
                float o0 = elu(p1a.x + p2a.x + rad * w0.x + ea.x * w1.x + ea.y * w2.x + ea.z * w3.x + ea.w * w4.x + bb.x);
                float o1 = elu(p1a.y + p2a.y + rad * w0.y + ea.x * w1.y + ea.y * w2.y + ea.z * w3.y + ea.w * w4.y + bb.y);
                float o2 = elu(p1b.x + p2b.x + rad * w0.z + ea.x * w1.z + ea.y * w2.z + ea.z * w3.z + ea.w * w4.z + bb.z);
                float o3 = elu(p1b.y + p2b.y + rad * w0.w + ea.x * w1.w + ea.y * w2.w + ea.z * w3.w + ea.w * w4.w + bb.w);
                pa[s * 2 + 0] = __floats2half2_rn(o0, o1);
                pa[s * 2 + 1] = __floats2half2_rn(o2, o3);
            }
        }
    }
    CP_WAIT0();
    __syncthreads();

    using namespace nvcuda::wmma;
    {
        int m0 = wid * 16;
        fragment<accumulator, 16, 16, 16, float> acc[8];
#pragma unroll
        for (int j = 0; j < 8; j++) fill_fragment(acc[j], 0.f);

#pragma unroll
        for (int k = 0; k < 8; k++) {
            fragment<matrix_a, 16, 16, 16, __half, row_major> a;
            load_matrix_sync(a, sA + m0 * AST + k * 16, AST);
#pragma unroll
            for (int nf = 0; nf < 8; nf++) {
                fragment<matrix_b, 16, 16, 16, __half, row_major> b;
                load_matrix_sync(b, sB + (k * 16) * AST + nf * 16, AST);
                mma_sync(acc[nf], a, b, acc[nf]);
            }
        }

        __syncthreads();
#pragma unroll
        for (int nf = 0; nf < 8; nf++)
            store_matrix_sync(sD + m0 * DSTR + nf * 16, acc[nf], DSTR, mem_row_major);
    }
    __syncthreads();

    {
        int ct = tid & 15, eg = tid >> 4;
        int jb = ct * 8;
        float b2v[8];
#pragma unroll
        for (int k = 0; k < 8; k++) b2v[k] = sB2[jb + k];
        float run[8];
#pragma unroll
        for (int k = 0; k < 8; k++) run[k] = 0.f;
        int cur = sRow[eg * 8];
#pragma unroll
        for (int i = 0; i < 8; i++) {
            int m = eg * 8 + i;
            int rr = sRow[m];
            if (rr != cur) {
                float* dst = g_agg + (size_t)cur * HID + jb;
                red4(dst, run[0], run[1], run[2], run[3]);
                red4(dst + 4, run[4], run[5], run[6], run[7]);
#pragma unroll
                for (int k = 0; k < 8; k++) run[k] = 0.f;
                cur = rr;
            }
            const float* sd = sD + m * DSTR + jb;
#pragma unroll
            for (int k = 0; k < 8; k++) run[k] += elu(sd[k] + b2v[k]);
        }
        float* dst = g_agg + (size_t)cur * HID + jb;
        red4(dst, run[0], run[1], run[2], run[3]);
        red4(dst + 4, run[4], run[5], run[6], run[7]);
    }
}

// ---------------- final head ----------------
__global__ void final_kernel(const float* __restrict__ label,
                             const float* __restrict__ eps,
                             const float* __restrict__ mu_w, const float* __restrict__ mu_b,
                             const float* __restrict__ var_w, const float* __restrict__ var_b,
                             float* __restrict__ out) {
    int idx = blockIdx.x * 256 + threadIdx.x;
    if (idx >= NN * LATD) return;
    int n = idx >> 6, l = idx & 63;
    float am = mu_b[l], av = var_b[l];
    const float* hrow = g_h0buf + n * HID;
#pragma unroll 4
    for (int k = 0; k < HID; k++) {
        float hv = hrow[k];
        am += hv * mu_w[k * LATD + l];
        av += hv * var_w[k * LATD + l];
    }
#pragma unroll
    for (int c = 0; c < 7; c++) {
        float lv = label[n * 7 + c];
        am += lv * mu_w[(HID + c) * LATD + l];
        av += lv * var_w[(HID + c) * LATD + l];
    }
    out[idx] = am + 0.01f * eps[idx] * __expf(0.5f * av);
}

// ---------------- launch ----------------
extern "C" void kernel_launch(void* const* d_in, const int* in_sizes, int n_in,
                              void* d_out, int out_size) {
    const float* h0        = (const float*)d_in[0];
    const float* label     = (const float*)d_in[1];
    const float* x         = (const float*)d_in[2];
    const float* edge_attr = (const float*)d_in[3];
    const float* eps       = (const float*)d_in[4];
    const float* emb_w     = (const float*)d_in[5];
    const float* emb_b     = (const float*)d_in[6];
    const float* ew1       = (const float*)d_in[7];
    const float* eb1       = (const float*)d_in[8];
    const float* ew2       = (const float*)d_in[9];
    const float* eb2       = (const float*)d_in[10];
    const float* nw1       = (const float*)d_in[11];
    const float* nb1       = (const float*)d_in[12];
    const float* nw2       = (const float*)d_in[13];
    const float* nb2       = (const float*)d_in[14];
    const float* mu_w      = (const float*)d_in[15];
    const float* mu_b      = (const float*)d_in[16];
    const float* var_w     = (const float*)d_in[17];
    const float* var_b     = (const float*)d_in[18];
    const int*   edges     = (const int*)d_in[19];
    const int* rowp = edges;
    const int* colp = edges + NE;
    float* out = (float*)d_out;

    cudaFuncSetAttribute(edge_hmma_kernel, cudaFuncAttributeMaxDynamicSharedMemorySize, EDGE_SMEM_BYTES);
    cudaFuncSetAttribute(pre_f16_kernel, cudaFuncAttributeMaxDynamicSharedMemorySize, PRE_SMEM);
    cudaFuncSetAttribute(node_f16_kernel, cudaFuncAttributeMaxDynamicSharedMemorySize, NODE_SMEM);

    const int GGRID = (NN + 127) / 128;   // 391

    embed_kernel<<<(NN * HID + 255) / 256, 256>>>(h0, emb_w, emb_b);
    wf16prep_kernel<<<(196608 + 255) / 256, 256>>>(ew2, ew1, nw1, nw2);

    // counting sort of edges by source node (once per launch)
    sort_zero_kernel<<<(NN + 255) / 256, 256>>>();
    sort_hist_kernel<<<(NE + 255) / 256, 256>>>(rowp);
    sort_scan1_kernel<<<NB_SCAN, 512>>>();
    sort_scan2_kernel<<<1, 32>>>();
    sort_scan3_kernel<<<(NN + 255) / 256, 256>>>();
    sort_scatter_kernel<<<(NE + 255) / 256, 256>>>(rowp, colp, x, edge_attr);

    float *h0p, *h1p, *aggp;
    cudaGetSymbolAddress((void**)&h0p, g_h0buf);
    cudaGetSymbolAddress((void**)&h1p, g_h1buf);
    cudaGetSymbolAddress((void**)&aggp, g_agg);
    __half *p1p, *p2p, *e1f, *n1f, *n2f;
    cudaGetSymbolAddress((void**)&p1p, g_P1h);
    cudaGetSymbolAddress((void**)&p2p, g_P2h);
    cudaGetSymbolAddress((void**)&e1f, g_E1f16);
    cudaGetSymbolAddress((void**)&n1f, g_N1f16);
    cudaGetSymbolAddress((void**)&n2f, g_N2f16);

    for (int layer = 0; layer < 2; layer++) {
        float* hsrc_p = (layer == 0) ? h0p : h1p;
        float* hdst   = (layer == 0) ? h1p : h0p;

        zero_agg_kernel<<<(NN * HID / 4 + 255) / 256, 256>>>();

        pre_f16_kernel<<<dim3(GGRID, 2), 256, PRE_SMEM>>>(
            hsrc_p,
            e1f + (size_t)layer * 2 * HID * HID, p1p,
            e1f + ((size_t)layer * 2 + 1) * HID * HID, p2p);

        edge_hmma_kernel<<<NE / 128, 256, EDGE_SMEM_BYTES>>>(ew1, eb1, eb2, layer);

        node_f16_kernel<<<GGRID, 256, NODE_SMEM>>>(
            hsrc_p, aggp,
            n1f + (size_t)layer * 2 * HID * HID,
            n2f + (size_t)layer * HID * HID,
            nb1 + layer * HID, nb2 + layer * HID, hdst);
    }

    final_kernel<<<(NN * LATD + 255) / 256, 256>>>(label, eps, mu_w, mu_b,
                                                   var_w, var_b, out);
}

// round 15
// speedup vs baseline: 1.4819x; 1.0820x over previous
#include <cuda_runtime.h>
#include <cuda_fp16.h>
#include <mma.h>
#include <cstdint>

#define NN 50000
#define NE 800000
#define HID 128
#define LATD 64
#define IN_NODE 11
#define IN_EDGE 4
#define NB_SCAN 98   // ceil(50000/512)

// ---------------- device scratch ----------------
__device__ float g_h0buf[NN * HID];
__device__ float g_h1buf[NN * HID];
__device__ float g_agg[NN * HID];
__device__ __half g_P1h[NN * HID];
__device__ __half g_P2h[NN * HID];
// counting-sort scratch
__device__ int g_cnt[NN];
__device__ int g_off[NB_SCAN * 512];
__device__ int g_cur[NN];
__device__ int g_blksum[NB_SCAN];
__device__ int g_blkoff[NB_SCAN];
// permuted (row-sorted) edge arrays
__device__ int   g_rowS[NE];
__device__ int   g_colS[NE];
__device__ float g_radS[NE];
__device__ float4 g_eaS[NE];
// fp16 weights
__device__ __half g_Wf16[2][HID * HID];          // edge W2 [K][N]
__device__ __half g_E1f16[2][2][HID * HID];      // ew1 rows 0..255
__device__ __half g_N1f16[2][2 * HID * HID];     // node [wsum ; W1b] [256][128]
__device__ __half g_N2f16[2][HID * HID];         // node W2 [128][128]

__device__ __forceinline__ float elu(float v) {
    return v > 0.f ? v : (__expf(v) - 1.f);
}

__device__ __forceinline__ void red4(float* p, float a, float b, float c, float d) {
    asm volatile("red.global.add.v4.f32 [%0], {%1,%2,%3,%4};"
                 :: "l"(p), "f"(a), "f"(b), "f"(c), "f"(d) : "memory");
}

// cp.async helpers (16B)
__device__ __forceinline__ void cp16(void* smem_dst, const void* gsrc) {
    uint32_t d = (uint32_t)__cvta_generic_to_shared(smem_dst);
    asm volatile("cp.async.ca.shared.global [%0], [%1], 16;" :: "r"(d), "l"(gsrc) : "memory");
}
#define CP_COMMIT() asm volatile("cp.async.commit_group;" ::: "memory")
#define CP_WAIT0()  asm volatile("cp.async.wait_group 0;" ::: "memory")

// ---------------- small kernels ----------------
// embed also zeros g_agg (layer-0) and g_cnt (sort)
__global__ void embed_kernel(const float* __restrict__ h0,
                             const float* __restrict__ emb_w,
                             const float* __restrict__ emb_b) {
    int idx = blockIdx.x * 256 + threadIdx.x;
    if (idx >= NN * HID) return;
    int n = idx >> 7, j = idx & 127;
    float acc = emb_b[j];
#pragma unroll
    for (int k = 0; k < IN_NODE; k++)
        acc += h0[n * IN_NODE + k] * emb_w[k * HID + j];
    g_h0buf[idx] = acc;
    g_agg[idx] = 0.f;
    if (idx < NN) g_cnt[idx] = 0;
}

// fp16 weight prep: edge W2, ew1 rows 0..255, node N1 (wsum-folded), node N2
__global__ void wf16prep_kernel(const float* __restrict__ ew2,
                                const float* __restrict__ ew1,
                                const float* __restrict__ nw1,
                                const float* __restrict__ nw2) {
    int idx = blockIdx.x * 256 + threadIdx.x;
    if (idx >= 196608) return;
    if (idx < 32768) {
        int layer = idx >> 14, rem = idx & 16383;
        g_Wf16[layer][rem] = __float2half(ew2[layer * HID * HID + rem]);
    } else if (idx < 98304) {
        int t = idx - 32768;
        int l = t >> 15, rest = t & 32767;
        int y = rest >> 14, r2 = rest & 16383;
        g_E1f16[l][y][r2] =
            __float2half(ew1[(l * 261 + y * 128 + (r2 >> 7)) * 128 + (r2 & 127)]);
    } else if (idx < 163840) {
        int t = idx - 98304;
        int l = t >> 15, rest = t & 32767;
        int k = rest >> 7, j = rest & 127;
        float v;
        if (k < 128)
            v = nw1[(l * 384 + k) * 128 + j] + nw1[(l * 384 + 256 + k) * 128 + j];
        else
            v = nw1[(l * 384 + 128 + (k - 128)) * 128 + j];
        g_N1f16[l][rest] = __float2half(v);
    } else {
        int t = idx - 163840;
        int l = t >> 14, rest = t & 16383;
        g_N2f16[l][rest] = __float2half(nw2[l * 16384 + rest]);
    }
}

// ---------------- counting sort of edges by row ----------------
__global__ void sort_hist_kernel(const int* __restrict__ row) {
    int e = blockIdx.x * 256 + threadIdx.x;
    if (e < NE) atomicAdd(&g_cnt[row[e]], 1);
}

__global__ void sort_scan1_kernel() {
    __shared__ int buf[512];
    int t = threadIdx.x;
    int i = blockIdx.x * 512 + t;
    int v = (i < NN) ? g_cnt[i] : 0;
    buf[t] = v;
    __syncthreads();
#pragma unroll
    for (int d = 1; d < 512; d <<= 1) {
        int x = (t >= d) ? buf[t - d] : 0;
        __syncthreads();
        buf[t] += x;
        __syncthreads();
    }
    g_off[i] = buf[t] - v;
    if (t == 511) g_blksum[blockIdx.x] = buf[511];
}

__global__ void sort_scan2_kernel() {
    if (threadIdx.x == 0) {
        int s = 0;
        for (int k = 0; k < NB_SCAN; k++) {
            g_blkoff[k] = s;
            s += g_blksum[k];
        }
    }
}

__global__ void sort_scan3_kernel() {
    int i = blockIdx.x * 256 + threadIdx.x;
    if (i < NN) {
        int o = g_off[i] + g_blkoff[i >> 9];
        g_off[i] = o;
        g_cur[i] = o;
    }
}

__global__ void sort_scatter_kernel(const int* __restrict__ row,
                                    const int* __restrict__ col,
                                    const float* __restrict__ x,
                                    const float* __restrict__ edge_attr) {
    int e = blockIdx.x * 256 + threadIdx.x;
    if (e >= NE) return;
    int r = row[e], c = col[e];
    float dx = x[r * 3 + 0] - x[c * 3 + 0];
    float dy = x[r * 3 + 1] - x[c * 3 + 1];
    float dz = x[r * 3 + 2] - x[c * 3 + 2];
    float rad = dx * dx + dy * dy + dz * dz;
    int pos = atomicAdd(&g_cur[r], 1);
    g_rowS[pos] = r;
    g_colS[pos] = c;
    g_radS[pos] = rad;
    g_eaS[pos] = *(const float4*)(edge_attr + (size_t)e * 4);
}

// ---------------- pre kernel: fused P1+P2, single A stage, fp16 single-pass ----------------
static constexpr int PF_ST = 136;   // fp16 stride
static constexpr int PD_ST = 68;    // f32 stride, half-width D scratch (over B1)
static constexpr int PR_A  = 0;         // 34816
static constexpr int PR_B1 = 34816;     // 34816 (D scratch unions here after MMA1)
static constexpr int PR_B2 = 69632;     // 34816
static constexpr int PRE_SMEM = 104448;

__global__ void __launch_bounds__(256, 2)
pre_f16_kernel(const float* __restrict__ hsrc,
               const __half* __restrict__ B1g, __half* __restrict__ P1,
               const __half* __restrict__ B2g, __half* __restrict__ P2) {
    extern __shared__ char smem[];
    __half* sA  = (__half*)(smem + PR_A);
    __half* sB1 = (__half*)(smem + PR_B1);
    __half* sB2 = (__half*)(smem + PR_B2);
    float*  sDh = (float*)(smem + PR_B1);

    int tid = threadIdx.x;
    int wid = tid >> 5;
    int n0 = blockIdx.x * 128;
    int r = tid >> 1, hf = tid & 1;
    int n = n0 + r;
    int m0 = wid * 16;

    // prefetch both B tables
    {
#pragma unroll
        for (int it = 0; it < 8; it++) {
            int i = tid + it * 256;
            int k = i >> 4, u = i & 15;
            cp16(sB1 + k * PF_ST + u * 8, B1g + (size_t)k * HID + u * 8);
            cp16(sB2 + k * PF_ST + u * 8, B2g + (size_t)k * HID + u * 8);
        }
        CP_COMMIT();
    }

    // stage A: fp32 h -> fp16 (once)
    if (n < NN) {
#pragma unroll
        for (int q = 0; q < 16; q++) {
            int col = hf * 64 + q * 4;
            float4 v = *(const float4*)(hsrc + (size_t)n * HID + col);
            __half2* pa = (__half2*)(sA + r * PF_ST + col);
            pa[0] = __floats2half2_rn(v.x, v.y);
            pa[1] = __floats2half2_rn(v.z, v.w);
        }
    } else {
#pragma unroll
        for (int q = 0; q < 16; q++) {
            int col = hf * 64 + q * 4;
            __half2* pa = (__half2*)(sA + r * PF_ST + col);
            pa[0] = __half2half2(__float2half(0.f));
            pa[1] = __half2half2(__float2half(0.f));
        }
    }
    CP_WAIT0();
    __syncthreads();

    using namespace nvcuda::wmma;
    fragment<accumulator, 16, 16, 16, float> acc[8];

#pragma unroll
    for (int pass = 0; pass < 2; pass++) {
        const __half* sB = pass ? sB2 : sB1;
        __half* P = pass ? P2 : P1;

#pragma unroll
        for (int j = 0; j < 8; j++) fill_fragment(acc[j], 0.f);
#pragma unroll
        for (int k = 0; k < 8; k++) {
            fragment<matrix_a, 16, 16, 16, __half, row_major> a;
            load_matrix_sync(a, sA + m0 * PF_ST + k * 16, PF_ST);
#pragma unroll
            for (int nf = 0; nf < 8; nf++) {
                fragment<matrix_b, 16, 16, 16, __half, row_major> b;
                load_matrix_sync(b, sB + (k * 16) * PF_ST + nf * 16, PF_ST);
                mma_sync(acc[nf], a, b, acc[nf]);
            }
        }
        __syncthreads();   // sB1 dead after pass-0 MMA -> D may use it

        // epilogue: two 64-col halves through sDh (over B1 region)
#pragma unroll
        for (int half = 0; half < 2; half++) {
#pragma unroll
            for (int nt = 0; nt < 4; nt++)
                store_matrix_sync(sDh + m0 * PD_ST + nt * 16, acc[half * 4 + nt],
                                  PD_ST, mem_row_major);
            __syncthreads();
            if (n < NN) {
#pragma unroll
                for (int q = 0; q < 4; q++) {
                    int c8 = hf * 32 + q * 8;
                    float4 v0 = *(const float4*)(sDh + r * PD_ST + c8);
                    float4 v1 = *(const float4*)(sDh + r * PD_ST + c8 + 4);
                    uint4 o;
                    ((__half2*)&o)[0] = __floats2half2_rn(v0.x, v0.y);
                    ((__half2*)&o)[1] = __floats2half2_rn(v0.z, v0.w);
                    ((__half2*)&o)[2] = __floats2half2_rn(v1.x, v1.y);
                    ((__half2*)&o)[3] = __floats2half2_rn(v1.z, v1.w);
                    *(uint4*)(P + (size_t)n * HID + half * 64 + c8) = o;
                }
            }
            __syncthreads();
        }
    }
}

// ---------------- fused node kernel: nf = elu([h|agg]@N1+b1); h' = nf@N2+b2 ----------------
// Also re-zeros g_agg rows after consuming them (replaces zero_agg for next layer).
static constexpr int NF_ST = 136;
static constexpr int ND_ST = 68;
static constexpr int NR_A  = 0;
static constexpr int NR_B  = 34816;
static constexpr int NR_D  = 69632;
static constexpr int NR_B1 = 104448;
static constexpr int NR_B2 = 104960;
static constexpr int NODE_SMEM = 105472;

__global__ void __launch_bounds__(256, 2)
node_f16_kernel(const float* __restrict__ hsrc, float* __restrict__ agg,
                const __half* __restrict__ N1, const __half* __restrict__ N2,
                const float* __restrict__ nb1, const float* __restrict__ nb2,
                float* __restrict__ hdst) {
    extern __shared__ char smem[];
    __half* sA  = (__half*)(smem + NR_A);
    __half* sB  = (__half*)(smem + NR_B);
    float*  sDh = (float*)(smem + NR_D);
    float*  sB1 = (float*)(smem + NR_B1);
    float*  sB2 = (float*)(smem + NR_B2);

    int tid = threadIdx.x;
    int wid = tid >> 5;
    int n0 = blockIdx.x * 128;
    int r = tid >> 1, hf = tid & 1;
    int n = n0 + r;
    int m0 = wid * 16;

    if (tid < HID) {
        sB1[tid] = nb1[tid];
        sB2[tid] = nb2[tid];
    }

    using namespace nvcuda::wmma;
    fragment<accumulator, 16, 16, 16, float> acc[8];
#pragma unroll
    for (int j = 0; j < 8; j++) fill_fragment(acc[j], 0.f);

    // GEMM1: K=256 in two 128-k chunks (chunk 0: h, chunk 1: agg, zeroed after read)
#pragma unroll
    for (int c = 0; c < 2; c++) {
        {
#pragma unroll
            for (int it = 0; it < 8; it++) {
                int i = tid + it * 256;
                int k = i >> 4, u = i & 15;
                cp16(sB + k * NF_ST + u * 8, N1 + (size_t)(c * 128 + k) * HID + u * 8);
            }
            CP_COMMIT();
        }
        {
            const float* src = c ? agg : hsrc;
            if (n < NN) {
#pragma unroll
                for (int q = 0; q < 16; q++) {
                    int col = hf * 64 + q * 4;
                    float4 v = *(const float4*)(src + (size_t)n * HID + col);
                    __half2* pa = (__half2*)(sA + r * NF_ST + col);
                    pa[0] = __floats2half2_rn(v.x, v.y);
                    pa[1] = __floats2half2_rn(v.z, v.w);
                    if (c)   // re-zero agg for the next layer's scatter
                        *(float4*)(agg + (size_t)n * HID + col) =
                            make_float4(0.f, 0.f, 0.f, 0.f);
                }
            } else {
#pragma unroll
                for (int q = 0; q < 16; q++) {
                    int col = hf * 64 + q * 4;
                    __half2* pa = (__half2*)(sA + r * NF_ST + col);
                    pa[0] = __half2half2(__float2half(0.f));
                    pa[1] = __half2half2(__float2half(0.f));
                }
            }
        }
        CP_WAIT0();
        __syncthreads();

#pragma unroll
        for (int k = 0; k < 8; k++) {
            fragment<matrix_a, 16, 16, 16, __half, row_major> a;
            load_matrix_sync(a, sA + m0 * NF_ST + k * 16, NF_ST);
#pragma unroll
            for (int nf = 0; nf < 8; nf++) {
                fragment<matrix_b, 16, 16, 16, __half, row_major> b;
                load_matrix_sync(b, sB + (k * 16) * NF_ST + nf * 16, NF_ST);
                mma_sync(acc[nf], a, b, acc[nf]);
            }
        }
        __syncthreads();
    }

    // prefetch N2 into sB (B region dead)
    {
#pragma unroll
        for (int it = 0; it < 8; it++) {
            int i = tid + it * 256;
            int k = i >> 4, u = i & 15;
            cp16(sB + k * NF_ST + u * 8, N2 + (size_t)k * HID + u * 8);
        }
        CP_COMMIT();
    }

    // nf = elu(D + b1) -> fp16 into sA, two 64-col halves via sDh
#pragma unroll
    for (int half = 0; half < 2; half++) {
#pragma unroll
        for (int nt = 0; nt < 4; nt++)
            store_matrix_sync(sDh + m0 * ND_ST + nt * 16, acc[half * 4 + nt], ND_ST, mem_row_major);
        __syncthreads();
        {
#pragma unroll
            for (int q = 0; q < 8; q++) {
                int col4 = hf * 32 + q * 4;
                float4 v = *(const float4*)(sDh + r * ND_ST + col4);
                int gc = half * 64 + col4;
                float b0 = sB1[gc + 0], b1v = sB1[gc + 1], b2v = sB1[gc + 2], b3v = sB1[gc + 3];
                float o0 = elu(v.x + b0), o1 = elu(v.y + b1v);
                float o2 = elu(v.z + b2v), o3 = elu(v.w + b3v);
                __half2* pa = (__half2*)(sA + r * NF_ST + gc);
                pa[0] = __floats2half2_rn(o0, o1);
                pa[1] = __floats2half2_rn(o2, o3);
            }
        }
        __syncthreads();
    }
    CP_WAIT0();
    __syncthreads();

    // GEMM2: h' = nf @ N2 (K=128)
#pragma unroll
    for (int j = 0; j < 8; j++) fill_fragment(acc[j], 0.f);
#pragma unroll
    for (int k = 0; k < 8; k++) {
        fragment<matrix_a, 16, 16, 16, __half, row_major> a;
        load_matrix_sync(a, sA + m0 * NF_ST + k * 16, NF_ST);
#pragma unroll
        for (int nf = 0; nf < 8; nf++) {
            fragment<matrix_b, 16, 16, 16, __half, row_major> b;
            load_matrix_sync(b, sB + (k * 16) * NF_ST + nf * 16, NF_ST);
            mma_sync(acc[nf], a, b, acc[nf]);
        }
    }
    __syncthreads();

    {
        float* sD = (float*)smem;
#pragma unroll
        for (int nf = 0; nf < 8; nf++)
            store_matrix_sync(sD + m0 * 132 + nf * 16, acc[nf], 132, mem_row_major);
        __syncthreads();
        if (n < NN) {
#pragma unroll
            for (int q = 0; q < 16; q++) {
                int col = hf * 64 + q * 4;
                float4 v = *(const float4*)(sD + r * 132 + col);
                v.x += sB2[col + 0];
                v.y += sB2[col + 1];
                v.z += sB2[col + 2];
                v.w += sB2[col + 3];
                *(float4*)(hdst + (size_t)n * HID + col) = v;
            }
        }
    }
}

// ---------------- edge kernel: single-pass fp16 MMA, wide fp16 P gather ----------------
static constexpr int AST = 136;
static constexpr int DSTR = 132;
static constexpr int SM_A  = 0;
static constexpr int SM_B  = 34816;
static constexpr int SM_WT = 69632;
static constexpr int SM_B1 = 72192;
static constexpr int SM_B2 = 72704;
static constexpr int SM_ROW = 73216;
static constexpr int EDGE_SMEM_BYTES = 73728;

__global__ void __launch_bounds__(256, 2)
edge_hmma_kernel(const float* __restrict__ ew1, const float* __restrict__ eb1,
                 const float* __restrict__ eb2, int layer) {
    extern __shared__ char smem[];
    __half* sA = (__half*)(smem + SM_A);
    __half* sB = (__half*)(smem + SM_B);
    float* sD  = (float*)smem;
    float* sWT = (float*)(smem + SM_WT);
    float* sB1 = (float*)(smem + SM_B1);
    float* sB2 = (float*)(smem + SM_B2);
    int*   sRow = (int*)(smem + SM_ROW);

    int tid = threadIdx.x;
    int wid = tid >> 5;
    int e0 = blockIdx.x * 128;

    {
        const __half* gW = g_Wf16[layer];
#pragma unroll
        for (int it = 0; it < 8; it++) {
            int i = tid + it * 256;
            int k = i >> 4, u = i & 15;
            cp16(sB + k * AST + u * 8, gW + k * HID + u * 8);
        }
        CP_COMMIT();
    }

    for (int i = tid; i < 5 * HID; i += 256) sWT[i] = ew1[(layer * 261 + 2 * HID) * HID + i];
    if (tid < HID) {
        sB1[tid] = eb1[layer * HID + tid];
        sB2[tid] = eb2[layer * HID + tid];
    }
    if (tid < 128) sRow[tid] = g_rowS[e0 + tid];
    __syncthreads();

    {
        int m = tid >> 1, hf = tid & 1;
        int e = e0 + m;
        int r = sRow[m], c = g_colS[e];
        float rad = g_radS[e];
        float4 ea = g_eaS[e];
        const __half* p1r = g_P1h + (size_t)r * HID;
        const __half* p2r = g_P2h + (size_t)c * HID;
#pragma unroll
        for (int q = 0; q < 8; q++) {
            int jb = hf * 64 + q * 8;
            uint4 u1 = *(const uint4*)(p1r + jb);
            uint4 u2 = *(const uint4*)(p2r + jb);
            const __half2* h1 = (const __half2*)&u1;
            const __half2* h2 = (const __half2*)&u2;
            __half2* pa = (__half2*)(sA + m * AST + jb);
#pragma unroll
            for (int s = 0; s < 2; s++) {
                int j4 = jb + s * 4;
                float2 p1a = __half22float2(h1[s * 2 + 0]);
                float2 p1b = __half22float2(h1[s * 2 + 1]);
                float2 p2a = __half22float2(h2[s * 2 + 0]);
                float2 p2b = __half22float2(h2[s * 2 + 1]);
                float4 w0 = *(const float4*)(sWT + 0 * HID + j4);
                float4 w1 = *(const float4*)(sWT + 1 * HID + j4);
                float4 w2 = *(const float4*)(sWT + 2 * HID + j4);
                float4 w3 = *(const float4*)(sWT + 3 * HID + j4);
                float4 w4 = *(const float4*)(sWT + 4 * HID + j4);
                float4 bb = *(const float4*)(sB1 + j4);
                float o0 = elu(p1a.x + p2a.x + rad * w0.x + ea.x * w1.x + ea.y * w2.x + ea.z * w3.x + ea.w * w4.x + bb.x);
                float o1 = elu(p1a.y + p2a.y + rad * w0.y + ea.x * w1.y + ea.y * w2.y + ea.z * w3.y + ea.w * w4.y + bb.y);
                float o2 = elu(p1b.x + p2b.x + rad * w0.z + ea.x * w1.z + ea.y * w2.z + ea.z * w3.z + ea.w * w4.z + bb.z);
                float o3 = elu(p1b.y + p2b.y + rad * w0.w + ea.x * w1.w + ea.y * w2.w + ea.z * w3.w + ea.w * w4.w + bb.w);
                pa[s * 2 + 0] = __floats2half2_rn(o0, o1);
                pa[s * 2 + 1] = __floats2half2_rn(o2, o3);
            }
        }
    }
    CP_WAIT0();
    __syncthreads();

    using namespace nvcuda::wmma;
    {
        int m0 = wid * 16;
        fragment<accumulator, 16, 16, 16, float> acc[8];
#pragma unroll
        for (int j = 0; j < 8; j++) fill_fragment(acc[j], 0.f);

#pragma unroll
        for (int k = 0; k < 8; k++) {
            fragment<matrix_a, 16, 16, 16, __half, row_major> a;
            load_matrix_sync(a, sA + m0 * AST + k * 16, AST);
#pragma unroll
            for (int nf = 0; nf < 8; nf++) {
                fragment<matrix_b, 16, 16, 16, __half, row_major> b;
                load_matrix_sync(b, sB + (k * 16) * AST + nf * 16, AST);
                mma_sync(acc[nf], a, b, acc[nf]);
            }
        }

        __syncthreads();
#pragma unroll
        for (int nf = 0; nf < 8; nf++)
            store_matrix_sync(sD + m0 * DSTR + nf * 16, acc[nf], DSTR, mem_row_major);
    }
    __syncthreads();

    {
        int ct = tid & 15, eg = tid >> 4;
        int jb = ct * 8;
        float b2v[8];
#pragma unroll
        for (int k = 0; k < 8; k++) b2v[k] = sB2[jb + k];
        float run[8];
#pragma unroll
        for (int k = 0; k < 8; k++) run[k] = 0.f;
        int cur = sRow[eg * 8];
#pragma unroll
        for (int i = 0; i < 8; i++) {
            int m = eg * 8 + i;
            int rr = sRow[m];
            if (rr != cur) {
                float* dst = g_agg + (size_t)cur * HID + jb;
                red4(dst, run[0], run[1], run[2], run[3]);
                red4(dst + 4, run[4], run[5], run[6], run[7]);
#pragma unroll
                for (int k = 0; k < 8; k++) run[k] = 0.f;
                cur = rr;
            }
            const float* sd = sD + m * DSTR + jb;
#pragma unroll
            for (int k = 0; k < 8; k++) run[k] += elu(sd[k] + b2v[k]);
        }
        float* dst = g_agg + (size_t)cur * HID + jb;
        red4(dst, run[0], run[1], run[2], run[3]);
        red4(dst + 4, run[4], run[5], run[6], run[7]);
    }
}

// ---------------- final head (vectorized: 16 threads/node, float4 accesses) ----------------
__global__ void final_kernel(const float* __restrict__ label,
                             const float* __restrict__ eps,
                             const float* __restrict__ mu_w, const float* __restrict__ mu_b,
                             const float* __restrict__ var_w, const float* __restrict__ var_b,
                             float* __restrict__ out) {
    int idx = blockIdx.x * 256 + threadIdx.x;
    if (idx >= NN * 16) return;
    int n = idx >> 4, g = idx & 15;
    float4 am = *(const float4*)(mu_b + g * 4);
    float4 av = *(const float4*)(var_b + g * 4);
    const float* hrow = g_h0buf + (size_t)n * HID;
#pragma unroll 4
    for (int k = 0; k < HID; k++) {
        float hv = hrow[k];
        float4 mw = *(const float4*)(mu_w + k * LATD + g * 4);
        float4 vw = *(const float4*)(var_w + k * LATD + g * 4);
        am.x += hv * mw.x; am.y += hv * mw.y; am.z += hv * mw.z; am.w += hv * mw.w;
        av.x += hv * vw.x; av.y += hv * vw.y; av.z += hv * vw.z; av.w += hv * vw.w;
    }
#pragma unroll
    for (int c = 0; c < 7; c++) {
        float lv = label[n * 7 + c];
        float4 mw = *(const float4*)(mu_w + (HID + c) * LATD + g * 4);
        float4 vw = *(const float4*)(var_w + (HID + c) * LATD + g * 4);
        am.x += lv * mw.x; am.y += lv * mw.y; am.z += lv * mw.z; am.w += lv * mw.w;
        av.x += lv * vw.x; av.y += lv * vw.y; av.z += lv * vw.z; av.w += lv * vw.w;
    }
    float4 ep = *(const float4*)(eps + (size_t)n * LATD + g * 4);
    float4 o;
    o.x = am.x + 0.01f * ep.x * __expf(0.5f * av.x);
    o.y = am.y + 0.01f * ep.y * __expf(0.5f * av.y);
    o.z = am.z + 0.01f * ep.z * __expf(0.5f * av.z);
    o.w = am.w + 0.01f * ep.w * __expf(0.5f * av.w);
    *(float4*)(out + (size_t)n * LATD + g * 4) = o;
}

// ---------------- launch ----------------
extern "C" void kernel_launch(void* const* d_in, const int* in_sizes, int n_in,
                              void* d_out, int out_size) {
    const float* h0        = (const float*)d_in[0];
    const float* label     = (const float*)d_in[1];
    const float* x         = (const float*)d_in[2];
    const float* edge_attr = (const float*)d_in[3];
    const float* eps       = (const float*)d_in[4];
    const float* emb_w     = (const float*)d_in[5];
    const float* emb_b     = (const float*)d_in[6];
    const float* ew1       = (const float*)d_in[7];
    const float* eb1       = (const float*)d_in[8];
    const float* ew2       = (const float*)d_in[9];
    const float* eb2       = (const float*)d_in[10];
    const float* nw1       = (const float*)d_in[11];
    const float* nb1       = (const float*)d_in[12];
    const float* nw2       = (const float*)d_in[13];
    const float* nb2       = (const float*)d_in[14];
    const float* mu_w      = (const float*)d_in[15];
    const float* mu_b      = (const float*)d_in[16];
    const float* var_w     = (const float*)d_in[17];
    const float* var_b     = (const float*)d_in[18];
    const int*   edges     = (const int*)d_in[19];
    const int* rowp = edges;
    const int* colp = edges + NE;
    float* out = (float*)d_out;

    cudaFuncSetAttribute(edge_hmma_kernel, cudaFuncAttributeMaxDynamicSharedMemorySize, EDGE_SMEM_BYTES);
    cudaFuncSetAttribute(pre_f16_kernel, cudaFuncAttributeMaxDynamicSharedMemorySize, PRE_SMEM);
    cudaFuncSetAttribute(node_f16_kernel, cudaFuncAttributeMaxDynamicSharedMemorySize, NODE_SMEM);

    const int GGRID = (NN + 127) / 128;   // 391

    embed_kernel<<<(NN * HID + 255) / 256, 256>>>(h0, emb_w, emb_b);
    wf16prep_kernel<<<(196608 + 255) / 256, 256>>>(ew2, ew1, nw1, nw2);

    // counting sort of edges by source node (g_cnt zeroed by embed)
    sort_hist_kernel<<<(NE + 255) / 256, 256>>>(rowp);
    sort_scan1_kernel<<<NB_SCAN, 512>>>();
    sort_scan2_kernel<<<1, 32>>>();
    sort_scan3_kernel<<<(NN + 255) / 256, 256>>>();
    sort_scatter_kernel<<<(NE + 255) / 256, 256>>>(rowp, colp, x, edge_attr);

    float *h0p, *h1p, *aggp;
    cudaGetSymbolAddress((void**)&h0p, g_h0buf);
    cudaGetSymbolAddress((void**)&h1p, g_h1buf);
    cudaGetSymbolAddress((void**)&aggp, g_agg);
    __half *p1p, *p2p, *e1f, *n1f, *n2f;
    cudaGetSymbolAddress((void**)&p1p, g_P1h);
    cudaGetSymbolAddress((void**)&p2p, g_P2h);
    cudaGetSymbolAddress((void**)&e1f, g_E1f16);
    cudaGetSymbolAddress((void**)&n1f, g_N1f16);
    cudaGetSymbolAddress((void**)&n2f, g_N2f16);

    for (int layer = 0; layer < 2; layer++) {
        float* hsrc_p = (layer == 0) ? h0p : h1p;
        float* hdst   = (layer == 0) ? h1p : h0p;

        // P1+P2 fused into one launch (g_agg pre-zeroed by embed / previous node)
        pre_f16_kernel<<<GGRID, 256, PRE_SMEM>>>(
            hsrc_p,
            e1f + (size_t)layer * 2 * HID * HID, p1p,
            e1f + ((size_t)layer * 2 + 1) * HID * HID, p2p);

        edge_hmma_kernel<<<NE / 128, 256, EDGE_SMEM_BYTES>>>(ew1, eb1, eb2, layer);

        node_f16_kernel<<<GGRID, 256, NODE_SMEM>>>(
            hsrc_p, aggp,
            n1f + (size_t)layer * 2 * HID * HID,
            n2f + (size_t)layer * HID * HID,
            nb1 + layer * HID, nb2 + layer * HID, hdst);
    }

    final_kernel<<<(NN * 16 + 255) / 256, 256>>>(label, eps, mu_w, mu_b,
                                                 var_w, var_b, out);
}

// round 16
// speedup vs baseline: 1.5421x; 1.0406x over previous
#include <cuda_runtime.h>
#include <cuda_fp16.h>
#include <mma.h>
#include <cstdint>

#define NN 50000
#define NE 800000
#define HID 128
#define LATD 64
#define IN_NODE 11
#define IN_EDGE 4
#define NB_SCAN 98   // ceil(50000/512)

// ---------------- device scratch ----------------
__device__ float g_h0buf[NN * HID];
__device__ float g_h1buf[NN * HID];
__device__ float g_agg[NN * HID];
__device__ __half g_P1h[NN * HID];
__device__ __half g_P2h[NN * HID];
// counting-sort scratch
__device__ int g_cnt[NN];
__device__ int g_off[NB_SCAN * 512];
__device__ int g_cur[NN];
__device__ int g_blksum[NB_SCAN];
// permuted (row-sorted) edge arrays
__device__ int   g_rowS[NE];
__device__ int   g_colS[NE];
__device__ float g_radS[NE];
__device__ float4 g_eaS[NE];
// fp16 weights
__device__ __half g_Wf16[2][HID * HID];          // edge W2 [K][N]
__device__ __half g_E1f16[2][2][HID * HID];      // ew1 rows 0..255
__device__ __half g_N1f16[2][2 * HID * HID];     // node [wsum ; W1b] [256][128]
__device__ __half g_N2f16[2][HID * HID];         // node W2 [128][128]

__device__ __forceinline__ float elu(float v) {
    return v > 0.f ? v : (__expf(v) - 1.f);
}

__device__ __forceinline__ void red4(float* p, float a, float b, float c, float d) {
    asm volatile("red.global.add.v4.f32 [%0], {%1,%2,%3,%4};"
                 :: "l"(p), "f"(a), "f"(b), "f"(c), "f"(d) : "memory");
}

// cp.async helpers (16B)
__device__ __forceinline__ void cp16(void* smem_dst, const void* gsrc) {
    uint32_t d = (uint32_t)__cvta_generic_to_shared(smem_dst);
    asm volatile("cp.async.ca.shared.global [%0], [%1], 16;" :: "r"(d), "l"(gsrc) : "memory");
}
#define CP_COMMIT() asm volatile("cp.async.commit_group;" ::: "memory")
#define CP_WAIT0()  asm volatile("cp.async.wait_group 0;" ::: "memory")

// ---------------- embed + weight prep + zero init (fused) ----------------
__global__ void embed_kernel(const float* __restrict__ h0,
                             const float* __restrict__ emb_w,
                             const float* __restrict__ emb_b,
                             const float* __restrict__ ew2,
                             const float* __restrict__ ew1,
                             const float* __restrict__ nw1,
                             const float* __restrict__ nw2) {
    int idx = blockIdx.x * 256 + threadIdx.x;
    if (idx >= NN * HID) return;
    int n = idx >> 7, j = idx & 127;
    float acc = emb_b[j];
#pragma unroll
    for (int k = 0; k < IN_NODE; k++)
        acc += h0[n * IN_NODE + k] * emb_w[k * HID + j];
    g_h0buf[idx] = acc;
    g_agg[idx] = 0.f;
    if (idx < NN) g_cnt[idx] = 0;

    // fp16 weight prep folded in (first 196608 indices)
    if (idx < 196608) {
        if (idx < 32768) {
            int layer = idx >> 14, rem = idx & 16383;
            g_Wf16[layer][rem] = __float2half(ew2[layer * HID * HID + rem]);
        } else if (idx < 98304) {
            int t = idx - 32768;
            int l = t >> 15, rest = t & 32767;
            int y = rest >> 14, r2 = rest & 16383;
            g_E1f16[l][y][r2] =
                __float2half(ew1[(l * 261 + y * 128 + (r2 >> 7)) * 128 + (r2 & 127)]);
        } else if (idx < 163840) {
            int t = idx - 98304;
            int l = t >> 15, rest = t & 32767;
            int k = rest >> 7, jj = rest & 127;
            float v;
            if (k < 128)
                v = nw1[(l * 384 + k) * 128 + jj] + nw1[(l * 384 + 256 + k) * 128 + jj];
            else
                v = nw1[(l * 384 + 128 + (k - 128)) * 128 + jj];
            g_N1f16[l][rest] = __float2half(v);
        } else {
            int t = idx - 163840;
            int l = t >> 14, rest = t & 16383;
            g_N2f16[l][rest] = __float2half(nw2[l * 16384 + rest]);
        }
    }
}

// ---------------- counting sort of edges by row ----------------
__global__ void sort_hist_kernel(const int* __restrict__ row) {
    int e = blockIdx.x * 256 + threadIdx.x;
    if (e < NE) atomicAdd(&g_cnt[row[e]], 1);
}

__global__ void sort_scan1_kernel() {
    __shared__ int buf[512];
    int t = threadIdx.x;
    int i = blockIdx.x * 512 + t;
    int v = (i < NN) ? g_cnt[i] : 0;
    buf[t] = v;
    __syncthreads();
#pragma unroll
    for (int d = 1; d < 512; d <<= 1) {
        int x = (t >= d) ? buf[t - d] : 0;
        __syncthreads();
        buf[t] += x;
        __syncthreads();
    }
    g_off[i] = buf[t] - v;
    if (t == 511) g_blksum[blockIdx.x] = buf[511];
}

// scan3 computes its own cross-block prefix (serial sum over <=97 entries)
__global__ void sort_scan3_kernel() {
    __shared__ int base;
    int i = blockIdx.x * 256 + threadIdx.x;
    if (threadIdx.x == 0) {
        int s = 0;
        int nb = blockIdx.x >> 1;   // 256-wide block -> 512-wide scan1 block index
        for (int k = 0; k < nb; k++) s += g_blksum[k];
        base = s;
    }
    __syncthreads();
    if (i < NN) g_cur[i] = g_off[i] + base;
}

__global__ void sort_scatter_kernel(const int* __restrict__ row,
                                    const int* __restrict__ col,
                                    const float* __restrict__ x,
                                    const float* __restrict__ edge_attr) {
    int e = blockIdx.x * 256 + threadIdx.x;
    if (e >= NE) return;
    int r = row[e], c = col[e];
    float dx = x[r * 3 + 0] - x[c * 3 + 0];
    float dy = x[r * 3 + 1] - x[c * 3 + 1];
    float dz = x[r * 3 + 2] - x[c * 3 + 2];
    float rad = dx * dx + dy * dy + dz * dz;
    int pos = atomicAdd(&g_cur[r], 1);
    g_rowS[pos] = r;
    g_colS[pos] = c;
    g_radS[pos] = rad;
    g_eaS[pos] = *(const float4*)(edge_attr + (size_t)e * 4);
}

// ---------------- pre kernel: fused P1+P2, single A stage, fp16 single-pass ----------------
static constexpr int PF_ST = 136;
static constexpr int PD_ST = 68;
static constexpr int PR_A  = 0;
static constexpr int PR_B1 = 34816;
static constexpr int PR_B2 = 69632;
static constexpr int PRE_SMEM = 104448;

__global__ void __launch_bounds__(256, 2)
pre_f16_kernel(const float* __restrict__ hsrc,
               const __half* __restrict__ B1g, __half* __restrict__ P1,
               const __half* __restrict__ B2g, __half* __restrict__ P2) {
    extern __shared__ char smem[];
    __half* sA  = (__half*)(smem + PR_A);
    __half* sB1 = (__half*)(smem + PR_B1);
    __half* sB2 = (__half*)(smem + PR_B2);
    float*  sDh = (float*)(smem + PR_B1);

    int tid = threadIdx.x;
    int wid = tid >> 5;
    int n0 = blockIdx.x * 128;
    int r = tid >> 1, hf = tid & 1;
    int n = n0 + r;
    int m0 = wid * 16;

    {
#pragma unroll
        for (int it = 0; it < 8; it++) {
            int i = tid + it * 256;
            int k = i >> 4, u = i & 15;
            cp16(sB1 + k * PF_ST + u * 8, B1g + (size_t)k * HID + u * 8);
            cp16(sB2 + k * PF_ST + u * 8, B2g + (size_t)k * HID + u * 8);
        }
        CP_COMMIT();
    }

    if (n < NN) {
#pragma unroll
        for (int q = 0; q < 16; q++) {
            int col = hf * 64 + q * 4;
            float4 v = *(const float4*)(hsrc + (size_t)n * HID + col);
            __half2* pa = (__half2*)(sA + r * PF_ST + col);
            pa[0] = __floats2half2_rn(v.x, v.y);
            pa[1] = __floats2half2_rn(v.z, v.w);
        }
    } else {
#pragma unroll
        for (int q = 0; q < 16; q++) {
            int col = hf * 64 + q * 4;
            __half2* pa = (__half2*)(sA + r * PF_ST + col);
            pa[0] = __half2half2(__float2half(0.f));
            pa[1] = __half2half2(__float2half(0.f));
        }
    }
    CP_WAIT0();
    __syncthreads();

    using namespace nvcuda::wmma;
    fragment<accumulator, 16, 16, 16, float> acc[8];

#pragma unroll
    for (int pass = 0; pass < 2; pass++) {
        const __half* sB = pass ? sB2 : sB1;
        __half* P = pass ? P2 : P1;

#pragma unroll
        for (int j = 0; j < 8; j++) fill_fragment(acc[j], 0.f);
#pragma unroll
        for (int k = 0; k < 8; k++) {
            fragment<matrix_a, 16, 16, 16, __half, row_major> a;
            load_matrix_sync(a, sA + m0 * PF_ST + k * 16, PF_ST);
#pragma unroll
            for (int nf = 0; nf < 8; nf++) {
                fragment<matrix_b, 16, 16, 16, __half, row_major> b;
                load_matrix_sync(b, sB + (k * 16) * PF_ST + nf * 16, PF_ST);
                mma_sync(acc[nf], a, b, acc[nf]);
            }
        }
        __syncthreads();

#pragma unroll
        for (int half = 0; half < 2; half++) {
#pragma unroll
            for (int nt = 0; nt < 4; nt++)
                store_matrix_sync(sDh + m0 * PD_ST + nt * 16, acc[half * 4 + nt],
                                  PD_ST, mem_row_major);
            __syncthreads();
            if (n < NN) {
#pragma unroll
                for (int q = 0; q < 4; q++) {
                    int c8 = hf * 32 + q * 8;
                    float4 v0 = *(const float4*)(sDh + r * PD_ST + c8);
                    float4 v1 = *(const float4*)(sDh + r * PD_ST + c8 + 4);
                    uint4 o;
                    ((__half2*)&o)[0] = __floats2half2_rn(v0.x, v0.y);
                    ((__half2*)&o)[1] = __floats2half2_rn(v0.z, v0.w);
                    ((__half2*)&o)[2] = __floats2half2_rn(v1.x, v1.y);
                    ((__half2*)&o)[3] = __floats2half2_rn(v1.z, v1.w);
                    *(uint4*)(P + (size_t)n * HID + half * 64 + c8) = o;
                }
            }
            __syncthreads();
        }
    }
}

// ---------------- fused node kernel ----------------
static constexpr int NF_ST = 136;
static constexpr int ND_ST = 68;
static constexpr int NR_A  = 0;
static constexpr int NR_B  = 34816;
static constexpr int NR_D  = 69632;
static constexpr int NR_B1 = 104448;
static constexpr int NR_B2 = 104960;
static constexpr int NODE_SMEM = 105472;

__global__ void __launch_bounds__(256, 2)
node_f16_kernel(const float* __restrict__ hsrc, float* __restrict__ agg,
                const __half* __restrict__ N1, const __half* __restrict__ N2,
                const float* __restrict__ nb1, const float* __restrict__ nb2,
                float* __restrict__ hdst) {
    extern __shared__ char smem[];
    __half* sA  = (__half*)(smem + NR_A);
    __half* sB  = (__half*)(smem + NR_B);
    float*  sDh = (float*)(smem + NR_D);
    float*  sB1 = (float*)(smem + NR_B1);
    float*  sB2 = (float*)(smem + NR_B2);

    int tid = threadIdx.x;
    int wid = tid >> 5;
    int n0 = blockIdx.x * 128;
    int r = tid >> 1, hf = tid & 1;
    int n = n0 + r;
    int m0 = wid * 16;

    if (tid < HID) {
        sB1[tid] = nb1[tid];
        sB2[tid] = nb2[tid];
    }

    using namespace nvcuda::wmma;
    fragment<accumulator, 16, 16, 16, float> acc[8];
#pragma unroll
    for (int j = 0; j < 8; j++) fill_fragment(acc[j], 0.f);

#pragma unroll
    for (int c = 0; c < 2; c++) {
        {
#pragma unroll
            for (int it = 0; it < 8; it++) {
                int i = tid + it * 256;
                int k = i >> 4, u = i & 15;
                cp16(sB + k * NF_ST + u * 8, N1 + (size_t)(c * 128 + k) * HID + u * 8);
            }
            CP_COMMIT();
        }
        {
            const float* src = c ? agg : hsrc;
            if (n < NN) {
#pragma unroll
                for (int q = 0; q < 16; q++) {
                    int col = hf * 64 + q * 4;
                    float4 v = *(const float4*)(src + (size_t)n * HID + col);
                    __half2* pa = (__half2*)(sA + r * NF_ST + col);
                    pa[0] = __floats2half2_rn(v.x, v.y);
                    pa[1] = __floats2half2_rn(v.z, v.w);
                    if (c)
                        *(float4*)(agg + (size_t)n * HID + col) =
                            make_float4(0.f, 0.f, 0.f, 0.f);
                }
            } else {
#pragma unroll
                for (int q = 0; q < 16; q++) {
                    int col = hf * 64 + q * 4;
                    __half2* pa = (__half2*)(sA + r * NF_ST + col);
                    pa[0] = __half2half2(__float2half(0.f));
                    pa[1] = __half2half2(__float2half(0.f));
                }
            }
        }
        CP_WAIT0();
        __syncthreads();

#pragma unroll
        for (int k = 0; k < 8; k++) {
            fragment<matrix_a, 16, 16, 16, __half, row_major> a;
            load_matrix_sync(a, sA + m0 * NF_ST + k * 16, NF_ST);
#pragma unroll
            for (int nf = 0; nf < 8; nf++) {
                fragment<matrix_b, 16, 16, 16, __half, row_major> b;
                load_matrix_sync(b, sB + (k * 16) * NF_ST + nf * 16, NF_ST);
                mma_sync(acc[nf], a, b, acc[nf]);
            }
        }
        __syncthreads();
    }

    {
#pragma unroll
        for (int it = 0; it < 8; it++) {
            int i = tid + it * 256;
            int k = i >> 4, u = i & 15;
            cp16(sB + k * NF_ST + u * 8, N2 + (size_t)k * HID + u * 8);
        }
        CP_COMMIT();
    }

#pragma unroll
    for (int half = 0; half < 2; half++) {
#pragma unroll
        for (int nt = 0; nt < 4; nt++)
            store_matrix_sync(sDh + m0 * ND_ST + nt * 16, acc[half * 4 + nt], ND_ST, mem_row_major);
        __syncthreads();
        {
#pragma unroll
            for (int q = 0; q < 8; q++) {
                int col4 = hf * 32 + q * 4;
                float4 v = *(const float4*)(sDh + r * ND_ST + col4);
                int gc = half * 64 + col4;
                float b0 = sB1[gc + 0], b1v = sB1[gc + 1], b2v = sB1[gc + 2], b3v = sB1[gc + 3];
                float o0 = elu(v.x + b0), o1 = elu(v.y + b1v);
                float o2 = elu(v.z + b2v), o3 = elu(v.w + b3v);
                __half2* pa = (__half2*)(sA + r * NF_ST + gc);
                pa[0] = __floats2half2_rn(o0, o1);
                pa[1] = __floats2half2_rn(o2, o3);
            }
        }
        __syncthreads();
    }
    CP_WAIT0();
    __syncthreads();

#pragma unroll
    for (int j = 0; j < 8; j++) fill_fragment(acc[j], 0.f);
#pragma unroll
    for (int k = 0; k < 8; k++) {
        fragment<matrix_a, 16, 16, 16, __half, row_major> a;
        load_matrix_sync(a, sA + m0 * NF_ST + k * 16, NF_ST);
#pragma unroll
        for (int nf = 0; nf < 8; nf++) {
            fragment<matrix_b, 16, 16, 16, __half, row_major> b;
            load_matrix_sync(b, sB + (k * 16) * NF_ST + nf * 16, NF_ST);
            mma_sync(acc[nf], a, b, acc[nf]);
        }
    }
    __syncthreads();

    {
        float* sD = (float*)smem;
#pragma unroll
        for (int nf = 0; nf < 8; nf++)
            store_matrix_sync(sD + m0 * 132 + nf * 16, acc[nf], 132, mem_row_major);
        __syncthreads();
        if (n < NN) {
#pragma unroll
            for (int q = 0; q < 16; q++) {
                int col = hf * 64 + q * 4;
                float4 v = *(const float4*)(sD + r * 132 + col);
                v.x += sB2[col + 0];
                v.y += sB2[col + 1];
                v.z += sB2[col + 2];
                v.w += sB2[col + 3];
                *(float4*)(hdst + (size_t)n * HID + col) = v;
            }
        }
    }
}

// ---------------- edge kernel: single-pass fp16 MMA, 2x4 warp tiling ----------------
static constexpr int AST = 136;
static constexpr int DSTR = 132;
static constexpr int SM_A  = 0;
static constexpr int SM_B  = 34816;
static constexpr int SM_WT = 69632;
static constexpr int SM_B1 = 72192;
static constexpr int SM_B2 = 72704;
static constexpr int SM_ROW = 73216;
static constexpr int EDGE_SMEM_BYTES = 73728;

__global__ void __launch_bounds__(256, 2)
edge_hmma_kernel(const float* __restrict__ ew1, const float* __restrict__ eb1,
                 const float* __restrict__ eb2, int layer) {
    extern __shared__ char smem[];
    __half* sA = (__half*)(smem + SM_A);
    __half* sB = (__half*)(smem + SM_B);
    float* sD  = (float*)smem;
    float* sWT = (float*)(smem + SM_WT);
    float* sB1 = (float*)(smem + SM_B1);
    float* sB2 = (float*)(smem + SM_B2);
    int*   sRow = (int*)(smem + SM_ROW);

    int tid = threadIdx.x;
    int wid = tid >> 5;
    int e0 = blockIdx.x * 128;

    {
        const __half* gW = g_Wf16[layer];
#pragma unroll
        for (int it = 0; it < 8; it++) {
            int i = tid + it * 256;
            int k = i >> 4, u = i & 15;
            cp16(sB + k * AST + u * 8, gW + k * HID + u * 8);
        }
        CP_COMMIT();
    }

    for (int i = tid; i < 5 * HID; i += 256) sWT[i] = ew1[(layer * 261 + 2 * HID) * HID + i];
    if (tid < HID) {
        sB1[tid] = eb1[layer * HID + tid];
        sB2[tid] = eb2[layer * HID + tid];
    }
    if (tid < 128) sRow[tid] = g_rowS[e0 + tid];
    __syncthreads();

    {
        int m = tid >> 1, hf = tid & 1;
        int e = e0 + m;
        int r = sRow[m], c = g_colS[e];
        float rad = g_radS[e];
        float4 ea = g_eaS[e];
        const __half* p1r = g_P1h + (size_t)r * HID;
        const __half* p2r = g_P2h + (size_t)c * HID;
#pragma unroll
        for (int q = 0; q < 8; q++) {
            int jb = hf * 64 + q * 8;
            uint4 u1 = *(const uint4*)(p1r + jb);
            uint4 u2 = *(const uint4*)(p2r + jb);
            const __half2* h1 = (const __half2*)&u1;
            const __half2* h2 = (const __half2*)&u2;
            __half2* pa = (__half2*)(sA + m * AST + jb);
#pragma unroll
            for (int s = 0; s < 2; s++) {
                int j4 = jb + s * 4;
                float2 p1a = __half22float2(h1[s * 2 + 0]);
                float2 p1b = __half22float2(h1[s * 2 + 1]);
                float2 p2a = __half22float2(h2[s * 2 + 0]);
                float2 p2b = __half22float2(h2[s * 2 + 1]);
                float4 w0 = *(const float4*)(sWT + 0 * HID + j4);
                float4 w1 = *(const float4*)(sWT + 1 * HID + j4);
                float4 w2 = *(const float4*)(sWT + 2 * HID + j4);
                float4 w3 = *(const float4*)(sWT + 3 * HID + j4);
                float4 w4 = *(const float4*)(sWT + 4 * HID + j4);
                float4 bb = *(const float4*)(sB1 + j4);
                float o0 = elu(p1a.x + p2a.x + rad * w0.x + ea.x * w1.x + ea.y * w2.x + ea.z * w3.x + ea.w * w4.x + bb.x);
                float o1 = elu(p1a.y + p2a.y + rad * w0.y + ea.x * w1.y + ea.y * w2.y + ea.z * w3.y + ea.w * w4.y + bb.y);
                float o2 = elu(p1b.x + p2b.x + rad * w0.z + ea.x * w1.z + ea.y * w2.z + ea.z * w3.z + ea.w * w4.z + bb.z);
                float o3 = elu(p1b.y + p2b.y + rad * w0.w + ea.x * w1.w + ea.y * w2.w + ea.z * w3.w + ea.w * w4.w + bb.w);
                pa[s * 2 + 0] = __floats2half2_rn(o0, o1);
                pa[s * 2 + 1] = __floats2half2_rn(o2, o3);
            }
        }
    }
    CP_WAIT0();
    __syncthreads();

    // single-pass fp16 MMA: 2x4 warp grid -> warp covers rows [(w>>1)*32,+32), cols [(w&1)*64,+64)
    using namespace nvcuda::wmma;
    {
        int m0 = (wid >> 1) * 32;
        int nb0 = (wid & 1) * 64;
        fragment<accumulator, 16, 16, 16, float> acc[2][4];
#pragma unroll
        for (int i2 = 0; i2 < 2; i2++)
#pragma unroll
            for (int j = 0; j < 4; j++) fill_fragment(acc[i2][j], 0.f);

#pragma unroll
        for (int k = 0; k < 8; k++) {
            fragment<matrix_a, 16, 16, 16, __half, row_major> a0, a1;
            load_matrix_sync(a0, sA + m0 * AST + k * 16, AST);
            load_matrix_sync(a1, sA + (m0 + 16) * AST + k * 16, AST);
#pragma unroll
            for (int j = 0; j < 4; j++) {
                fragment<matrix_b, 16, 16, 16, __half, row_major> b;
                load_matrix_sync(b, sB + (k * 16) * AST + nb0 + j * 16, AST);
                mma_sync(acc[0][j], a0, b, acc[0][j]);
                mma_sync(acc[1][j], a1, b, acc[1][j]);
            }
        }

        __syncthreads();   // A and B fully dead -> D may overwrite
#pragma unroll
        for (int i2 = 0; i2 < 2; i2++)
#pragma unroll
            for (int j = 0; j < 4; j++)
                store_matrix_sync(sD + (m0 + i2 * 16) * DSTR + nb0 + j * 16,
                                  acc[i2][j], DSTR, mem_row_major);
    }
    __syncthreads();

    {
        int ct = tid & 15, eg = tid >> 4;
        int jb = ct * 8;
        float b2v[8];
#pragma unroll
        for (int k = 0; k < 8; k++) b2v[k] = sB2[jb + k];
        float run[8];
#pragma unroll
        for (int k = 0; k < 8; k++) run[k] = 0.f;
        int cur = sRow[eg * 8];
#pragma unroll
        for (int i = 0; i < 8; i++) {
            int m = eg * 8 + i;
            int rr = sRow[m];
            if (rr != cur) {
                float* dst = g_agg + (size_t)cur * HID + jb;
                red4(dst, run[0], run[1], run[2], run[3]);
                red4(dst + 4, run[4], run[5], run[6], run[7]);
#pragma unroll
                for (int k = 0; k < 8; k++) run[k] = 0.f;
                cur = rr;
            }
            const float* sd = sD + m * DSTR + jb;
#pragma unroll
            for (int k = 0; k < 8; k++) run[k] += elu(sd[k] + b2v[k]);
        }
        float* dst = g_agg + (size_t)cur * HID + jb;
        red4(dst, run[0], run[1], run[2], run[3]);
        red4(dst + 4, run[4], run[5], run[6], run[7]);
    }
}

// ---------------- final head (vectorized) ----------------
__global__ void final_kernel(const float* __restrict__ label,
                             const float* __restrict__ eps,
                             const float* __restrict__ mu_w, const float* __restrict__ mu_b,
                             const float* __restrict__ var_w, const float* __restrict__ var_b,
                             float* __restrict__ out) {
    int idx = blockIdx.x * 256 + threadIdx.x;
    if (idx >= NN * 16) return;
    int n = idx >> 4, g = idx & 15;
    float4 am = *(const float4*)(mu_b + g * 4);
    float4 av = *(const float4*)(var_b + g * 4);
    const float* hrow = g_h0buf + (size_t)n * HID;
#pragma unroll 4
    for (int k = 0; k < HID; k++) {
        float hv = hrow[k];
        float4 mw = *(const float4*)(mu_w + k * LATD + g * 4);
        float4 vw = *(const float4*)(var_w + k * LATD + g * 4);
        am.x += hv * mw.x; am.y += hv * mw.y; am.z += hv * mw.z; am.w += hv * mw.w;
        av.x += hv * vw.x; av.y += hv * vw.y; av.z += hv * vw.z; av.w += hv * vw.w;
    }
#pragma unroll
    for (int c = 0; c < 7; c++) {
        float lv = label[n * 7 + c];
        float4 mw = *(const float4*)(mu_w + (HID + c) * LATD + g * 4);
        float4 vw = *(const float4*)(var_w + (HID + c) * LATD + g * 4);
        am.x += lv * mw.x; am.y += lv * mw.y; am.z += lv * mw.z; am.w += lv * mw.w;
        av.x += lv * vw.x; av.y += lv * vw.y; av.z += lv * vw.z; av.w += lv * vw.w;
    }
    float4 ep = *(const float4*)(eps + (size_t)n * LATD + g * 4);
    float4 o;
    o.x = am.x + 0.01f * ep.x * __expf(0.5f * av.x);
    o.y = am.y + 0.01f * ep.y * __expf(0.5f * av.y);
    o.z = am.z + 0.01f * ep.z * __expf(0.5f * av.z);
    o.w = am.w + 0.01f * ep.w * __expf(0.5f * av.w);
    *(float4*)(out + (size_t)n * LATD + g * 4) = o;
}

// ---------------- launch ----------------
extern "C" void kernel_launch(void* const* d_in, const int* in_sizes, int n_in,
                              void* d_out, int out_size) {
    const float* h0        = (const float*)d_in[0];
    const float* label     = (const float*)d_in[1];
    const float* x         = (const float*)d_in[2];
    const float* edge_attr = (const float*)d_in[3];
    const float* eps       = (const float*)d_in[4];
    const float* emb_w     = (const float*)d_in[5];
    const float* emb_b     = (const float*)d_in[6];
    const float* ew1       = (const float*)d_in[7];
    const float* eb1       = (const float*)d_in[8];
    const float* ew2       = (const float*)d_in[9];
    const float* eb2       = (const float*)d_in[10];
    const float* nw1       = (const float*)d_in[11];
    const float* nb1       = (const float*)d_in[12];
    const float* nw2       = (const float*)d_in[13];
    const float* nb2       = (const float*)d_in[14];
    const float* mu_w      = (const float*)d_in[15];
    const float* mu_b      = (const float*)d_in[16];
    const float* var_w     = (const float*)d_in[17];
    const float* var_b     = (const float*)d_in[18];
    const int*   edges     = (const int*)d_in[19];
    const int* rowp = edges;
    const int* colp = edges + NE;
    float* out = (float*)d_out;

    cudaFuncSetAttribute(edge_hmma_kernel, cudaFuncAttributeMaxDynamicSharedMemorySize, EDGE_SMEM_BYTES);
    cudaFuncSetAttribute(pre_f16_kernel, cudaFuncAttributeMaxDynamicSharedMemorySize, PRE_SMEM);
    cudaFuncSetAttribute(node_f16_kernel, cudaFuncAttributeMaxDynamicSharedMemorySize, NODE_SMEM);

    const int GGRID = (NN + 127) / 128;   // 391

    embed_kernel<<<(NN * HID + 255) / 256, 256>>>(h0, emb_w, emb_b, ew2, ew1, nw1, nw2);

    // counting sort of edges by source node (g_cnt zeroed by embed)
    sort_hist_kernel<<<(NE + 255) / 256, 256>>>(rowp);
    sort_scan1_kernel<<<NB_SCAN, 512>>>();
    sort_scan3_kernel<<<(NN + 255) / 256, 256>>>();
    sort_scatter_kernel<<<(NE + 255) / 256, 256>>>(rowp, colp, x, edge_attr);

    float *h0p, *h1p, *aggp;
    cudaGetSymbolAddress((void**)&h0p, g_h0buf);
    cudaGetSymbolAddress((void**)&h1p, g_h1buf);
    cudaGetSymbolAddress((void**)&aggp, g_agg);
    __half *p1p, *p2p, *e1f, *n1f, *n2f;
    cudaGetSymbolAddress((void**)&p1p, g_P1h);
    cudaGetSymbolAddress((void**)&p2p, g_P2h);
    cudaGetSymbolAddress((void**)&e1f, g_E1f16);
    cudaGetSymbolAddress((void**)&n1f, g_N1f16);
    cudaGetSymbolAddress((void**)&n2f, g_N2f16);

    for (int layer = 0; layer < 2; layer++) {
        float* hsrc_p = (layer == 0) ? h0p : h1p;
        float* hdst   = (layer == 0) ? h1p : h0p;

        pre_f16_kernel<<<GGRID, 256, PRE_SMEM>>>(
            hsrc_p,
            e1f + (size_t)layer * 2 * HID * HID, p1p,
            e1f + ((size_t)layer * 2 + 1) * HID * HID, p2p);

        edge_hmma_kernel<<<NE / 128, 256, EDGE_SMEM_BYTES>>>(ew1, eb1, eb2, layer);

        node_f16_kernel<<<GGRID, 256, NODE_SMEM>>>(
            hsrc_p, aggp,
            n1f + (size_t)layer * 2 * HID * HID,
            n2f + (size_t)layer * HID * HID,
            nb1 + layer * HID, nb2 + layer * HID, hdst);
    }

    final_kernel<<<(NN * 16 + 255) / 256, 256>>>(label, eps, mu_w, mu_b,
                                                 var_w, var_b, out);
}

// round 17
// speedup vs baseline: 1.5898x; 1.0310x over previous
#include <cuda_runtime.h>
#include <cuda_fp16.h>
#include <mma.h>
#include <cstdint>

#define NN 50000
#define NE 800000
#define HID 128
#define LATD 64
#define IN_NODE 11
#define IN_EDGE 4
#define NB_SCAN 98     // ceil(50000/512)
#define NTILE 6250     // NE / 128
#define EGRID 304      // persistent edge CTAs (2 per SM, 152 SMs)

// ---------------- device scratch ----------------
__device__ float g_h0buf[NN * HID];
__device__ float g_h1buf[NN * HID];
__device__ float g_agg[NN * HID];
__device__ __half g_P1h[NN * HID];
__device__ __half g_P2h[NN * HID];
// counting-sort scratch
__device__ int g_cnt[NN];
__device__ int g_off[NB_SCAN * 512];
__device__ int g_cur[NN];
__device__ int g_blksum[NB_SCAN];
// permuted (row-sorted) edge arrays
__device__ int   g_rowS[NE];
__device__ int   g_colS[NE];
__device__ float g_radS[NE];
__device__ float4 g_eaS[NE];
// fp16 weights
__device__ __half g_Wf16[2][HID * HID];          // edge W2 [K][N]
__device__ __half g_E1f16[2][2][HID * HID];      // ew1 rows 0..255
__device__ __half g_N1f16[2][2 * HID * HID];     // node [wsum ; W1b] [256][128]
__device__ __half g_N2f16[2][HID * HID];         // node W2 [128][128]

__device__ __forceinline__ float elu(float v) {
    return v > 0.f ? v : (__expf(v) - 1.f);
}

__device__ __forceinline__ void red4(float* p, float a, float b, float c, float d) {
    asm volatile("red.global.add.v4.f32 [%0], {%1,%2,%3,%4};"
                 :: "l"(p), "f"(a), "f"(b), "f"(c), "f"(d) : "memory");
}

// cp.async helpers (16B)
__device__ __forceinline__ void cp16(void* smem_dst, const void* gsrc) {
    uint32_t d = (uint32_t)__cvta_generic_to_shared(smem_dst);
    asm volatile("cp.async.ca.shared.global [%0], [%1], 16;" :: "r"(d), "l"(gsrc) : "memory");
}
#define CP_COMMIT() asm volatile("cp.async.commit_group;" ::: "memory")
#define CP_WAIT0()  asm volatile("cp.async.wait_group 0;" ::: "memory")

// ---------------- embed + weight prep + zero init (fused) ----------------
__global__ void embed_kernel(const float* __restrict__ h0,
                             const float* __restrict__ emb_w,
                             const float* __restrict__ emb_b,
                             const float* __restrict__ ew2,
                             const float* __restrict__ ew1,
                             const float* __restrict__ nw1,
                             const float* __restrict__ nw2) {
    int idx = blockIdx.x * 256 + threadIdx.x;
    if (idx >= NN * HID) return;
    int n = idx >> 7, j = idx & 127;
    float acc = emb_b[j];
#pragma unroll
    for (int k = 0; k < IN_NODE; k++)
        acc += h0[n * IN_NODE + k] * emb_w[k * HID + j];
    g_h0buf[idx] = acc;
    g_agg[idx] = 0.f;
    if (idx < NN) g_cnt[idx] = 0;

    if (idx < 196608) {
        if (idx < 32768) {
            int layer = idx >> 14, rem = idx & 16383;
            g_Wf16[layer][rem] = __float2half(ew2[layer * HID * HID + rem]);
        } else if (idx < 98304) {
            int t = idx - 32768;
            int l = t >> 15, rest = t & 32767;
            int y = rest >> 14, r2 = rest & 16383;
            g_E1f16[l][y][r2] =
                __float2half(ew1[(l * 261 + y * 128 + (r2 >> 7)) * 128 + (r2 & 127)]);
        } else if (idx < 163840) {
            int t = idx - 98304;
            int l = t >> 15, rest = t & 32767;
            int k = rest >> 7, jj = rest & 127;
            float v;
            if (k < 128)
                v = nw1[(l * 384 + k) * 128 + jj] + nw1[(l * 384 + 256 + k) * 128 + jj];
            else
                v = nw1[(l * 384 + 128 + (k - 128)) * 128 + jj];
            g_N1f16[l][rest] = __float2half(v);
        } else {
            int t = idx - 163840;
            int l = t >> 14, rest = t & 16383;
            g_N2f16[l][rest] = __float2half(nw2[l * 16384 + rest]);
        }
    }
}

// ---------------- counting sort of edges by row ----------------
__global__ void sort_hist_kernel(const int* __restrict__ row) {
    int e = blockIdx.x * 256 + threadIdx.x;
    if (e < NE) atomicAdd(&g_cnt[row[e]], 1);
}

__global__ void sort_scan1_kernel() {
    __shared__ int buf[512];
    int t = threadIdx.x;
    int i = blockIdx.x * 512 + t;
    int v = (i < NN) ? g_cnt[i] : 0;
    buf[t] = v;
    __syncthreads();
#pragma unroll
    for (int d = 1; d < 512; d <<= 1) {
        int x = (t >= d) ? buf[t - d] : 0;
        __syncthreads();
        buf[t] += x;
        __syncthreads();
    }
    g_off[i] = buf[t] - v;
    if (t == 511) g_blksum[blockIdx.x] = buf[511];
}

__global__ void sort_scan3_kernel() {
    __shared__ int base;
    int i = blockIdx.x * 256 + threadIdx.x;
    if (threadIdx.x == 0) {
        int s = 0;
        int nb = blockIdx.x >> 1;
        for (int k = 0; k < nb; k++) s += g_blksum[k];
        base = s;
    }
    __syncthreads();
    if (i < NN) g_cur[i] = g_off[i] + base;
}

__global__ void sort_scatter_kernel(const int* __restrict__ row,
                                    const int* __restrict__ col,
                                    const float* __restrict__ x,
                                    const float* __restrict__ edge_attr) {
    int e = blockIdx.x * 256 + threadIdx.x;
    if (e >= NE) return;
    int r = row[e], c = col[e];
    float dx = x[r * 3 + 0] - x[c * 3 + 0];
    float dy = x[r * 3 + 1] - x[c * 3 + 1];
    float dz = x[r * 3 + 2] - x[c * 3 + 2];
    float rad = dx * dx + dy * dy + dz * dz;
    int pos = atomicAdd(&g_cur[r], 1);
    g_rowS[pos] = r;
    g_colS[pos] = c;
    g_radS[pos] = rad;
    g_eaS[pos] = *(const float4*)(edge_attr + (size_t)e * 4);
}

// ---------------- pre kernel: fused P1+P2, single A stage, fp16 single-pass ----------------
static constexpr int PF_ST = 136;
static constexpr int PD_ST = 68;
static constexpr int PR_A  = 0;
static constexpr int PR_B1 = 34816;
static constexpr int PR_B2 = 69632;
static constexpr int PRE_SMEM = 104448;

__global__ void __launch_bounds__(256, 2)
pre_f16_kernel(const float* __restrict__ hsrc,
               const __half* __restrict__ B1g, __half* __restrict__ P1,
               const __half* __restrict__ B2g, __half* __restrict__ P2) {
    extern __shared__ char smem[];
    __half* sA  = (__half*)(smem + PR_A);
    __half* sB1 = (__half*)(smem + PR_B1);
    __half* sB2 = (__half*)(smem + PR_B2);
    float*  sDh = (float*)(smem + PR_B1);

    int tid = threadIdx.x;
    int wid = tid >> 5;
    int n0 = blockIdx.x * 128;
    int r = tid >> 1, hf = tid & 1;
    int n = n0 + r;
    int m0 = wid * 16;

    {
#pragma unroll
        for (int it = 0; it < 8; it++) {
            int i = tid + it * 256;
            int k = i >> 4, u = i & 15;
            cp16(sB1 + k * PF_ST + u * 8, B1g + (size_t)k * HID + u * 8);
            cp16(sB2 + k * PF_ST + u * 8, B2g + (size_t)k * HID + u * 8);
        }
        CP_COMMIT();
    }

    if (n < NN) {
#pragma unroll
        for (int q = 0; q < 16; q++) {
            int col = hf * 64 + q * 4;
            float4 v = *(const float4*)(hsrc + (size_t)n * HID + col);
            __half2* pa = (__half2*)(sA + r * PF_ST + col);
            pa[0] = __floats2half2_rn(v.x, v.y);
            pa[1] = __floats2half2_rn(v.z, v.w);
        }
    } else {
#pragma unroll
        for (int q = 0; q < 16; q++) {
            int col = hf * 64 + q * 4;
            __half2* pa = (__half2*)(sA + r * PF_ST + col);
            pa[0] = __half2half2(__float2half(0.f));
            pa[1] = __half2half2(__float2half(0.f));
        }
    }
    CP_WAIT0();
    __syncthreads();

    using namespace nvcuda::wmma;
    fragment<accumulator, 16, 16, 16, float> acc[8];

#pragma unroll
    for (int pass = 0; pass < 2; pass++) {
        const __half* sB = pass ? sB2 : sB1;
        __half* P = pass ? P2 : P1;

#pragma unroll
        for (int j = 0; j < 8; j++) fill_fragment(acc[j], 0.f);
#pragma unroll
        for (int k = 0; k < 8; k++) {
            fragment<matrix_a, 16, 16, 16, __half, row_major> a;
            load_matrix_sync(a, sA + m0 * PF_ST + k * 16, PF_ST);
#pragma unroll
            for (int nf = 0; nf < 8; nf++) {
                fragment<matrix_b, 16, 16, 16, __half, row_major> b;
                load_matrix_sync(b, sB + (k * 16) * PF_ST + nf * 16, PF_ST);
                mma_sync(acc[nf], a, b, acc[nf]);
            }
        }
        __syncthreads();

#pragma unroll
        for (int half = 0; half < 2; half++) {
#pragma unroll
            for (int nt = 0; nt < 4; nt++)
                store_matrix_sync(sDh + m0 * PD_ST + nt * 16, acc[half * 4 + nt],
                                  PD_ST, mem_row_major);
            __syncthreads();
            if (n < NN) {
#pragma unroll
                for (int q = 0; q < 4; q++) {
                    int c8 = hf * 32 + q * 8;
                    float4 v0 = *(const float4*)(sDh + r * PD_ST + c8);
                    float4 v1 = *(const float4*)(sDh + r * PD_ST + c8 + 4);
                    uint4 o;
                    ((__half2*)&o)[0] = __floats2half2_rn(v0.x, v0.y);
                    ((__half2*)&o)[1] = __floats2half2_rn(v0.z, v0.w);
                    ((__half2*)&o)[2] = __floats2half2_rn(v1.x, v1.y);
                    ((__half2*)&o)[3] = __floats2half2_rn(v1.z, v1.w);
                    *(uint4*)(P + (size_t)n * HID + half * 64 + c8) = o;
                }
            }
            __syncthreads();
        }
    }
}

// ---------------- fused node kernel ----------------
static constexpr int NF_ST = 136;
static constexpr int ND_ST = 68;
static constexpr int NR_A  = 0;
static constexpr int NR_B  = 34816;
static constexpr int NR_D  = 69632;
static constexpr int NR_B1 = 104448;
static constexpr int NR_B2 = 104960;
static constexpr int NODE_SMEM = 105472;

__global__ void __launch_bounds__(256, 2)
node_f16_kernel(const float* __restrict__ hsrc, float* __restrict__ agg,
                const __half* __restrict__ N1, const __half* __restrict__ N2,
                const float* __restrict__ nb1, const float* __restrict__ nb2,
                float* __restrict__ hdst) {
    extern __shared__ char smem[];
    __half* sA  = (__half*)(smem + NR_A);
    __half* sB  = (__half*)(smem + NR_B);
    float*  sDh = (float*)(smem + NR_D);
    float*  sB1 = (float*)(smem + NR_B1);
    float*  sB2 = (float*)(smem + NR_B2);

    int tid = threadIdx.x;
    int wid = tid >> 5;
    int n0 = blockIdx.x * 128;
    int r = tid >> 1, hf = tid & 1;
    int n = n0 + r;
    int m0 = wid * 16;

    if (tid < HID) {
        sB1[tid] = nb1[tid];
        sB2[tid] = nb2[tid];
    }

    using namespace nvcuda::wmma;
    fragment<accumulator, 16, 16, 16, float> acc[8];
#pragma unroll
    for (int j = 0; j < 8; j++) fill_fragment(acc[j], 0.f);

#pragma unroll
    for (int c = 0; c < 2; c++) {
        {
#pragma unroll
            for (int it = 0; it < 8; it++) {
                int i = tid + it * 256;
                int k = i >> 4, u = i & 15;
                cp16(sB + k * NF_ST + u * 8, N1 + (size_t)(c * 128 + k) * HID + u * 8);
            }
            CP_COMMIT();
        }
        {
            const float* src = c ? agg : hsrc;
            if (n < NN) {
#pragma unroll
                for (int q = 0; q < 16; q++) {
                    int col = hf * 64 + q * 4;
                    float4 v = *(const float4*)(src + (size_t)n * HID + col);
                    __half2* pa = (__half2*)(sA + r * NF_ST + col);
                    pa[0] = __floats2half2_rn(v.x, v.y);
                    pa[1] = __floats2half2_rn(v.z, v.w);
                    if (c)
                        *(float4*)(agg + (size_t)n * HID + col) =
                            make_float4(0.f, 0.f, 0.f, 0.f);
                }
            } else {
#pragma unroll
                for (int q = 0; q < 16; q++) {
                    int col = hf * 64 + q * 4;
                    __half2* pa = (__half2*)(sA + r * NF_ST + col);
                    pa[0] = __half2half2(__float2half(0.f));
                    pa[1] = __half2half2(__float2half(0.f));
                }
            }
        }
        CP_WAIT0();
        __syncthreads();

#pragma unroll
        for (int k = 0; k < 8; k++) {
            fragment<matrix_a, 16, 16, 16, __half, row_major> a;
            load_matrix_sync(a, sA + m0 * NF_ST + k * 16, NF_ST);
#pragma unroll
            for (int nf = 0; nf < 8; nf++) {
                fragment<matrix_b, 16, 16, 16, __half, row_major> b;
                load_matrix_sync(b, sB + (k * 16) * NF_ST + nf * 16, NF_ST);
                mma_sync(acc[nf], a, b, acc[nf]);
            }
        }
        __syncthreads();
    }

    {
#pragma unroll
        for (int it = 0; it < 8; it++) {
            int i = tid + it * 256;
            int k = i >> 4, u = i & 15;
            cp16(sB + k * NF_ST + u * 8, N2 + (size_t)k * HID + u * 8);
        }
        CP_COMMIT();
    }

#pragma unroll
    for (int half = 0; half < 2; half++) {
#pragma unroll
        for (int nt = 0; nt < 4; nt++)
            store_matrix_sync(sDh + m0 * ND_ST + nt * 16, acc[half * 4 + nt], ND_ST, mem_row_major);
        __syncthreads();
        {
#pragma unroll
            for (int q = 0; q < 8; q++) {
                int col4 = hf * 32 + q * 4;
                float4 v = *(const float4*)(sDh + r * ND_ST + col4);
                int gc = half * 64 + col4;
                float b0 = sB1[gc + 0], b1v = sB1[gc + 1], b2v = sB1[gc + 2], b3v = sB1[gc + 3];
                float o0 = elu(v.x + b0), o1 = elu(v.y + b1v);
                float o2 = elu(v.z + b2v), o3 = elu(v.w + b3v);
                __half2* pa = (__half2*)(sA + r * NF_ST + gc);
                pa[0] = __floats2half2_rn(o0, o1);
                pa[1] = __floats2half2_rn(o2, o3);
            }
        }
        __syncthreads();
    }
    CP_WAIT0();
    __syncthreads();

#pragma unroll
    for (int j = 0; j < 8; j++) fill_fragment(acc[j], 0.f);
#pragma unroll
    for (int k = 0; k < 8; k++) {
        fragment<matrix_a, 16, 16, 16, __half, row_major> a;
        load_matrix_sync(a, sA + m0 * NF_ST + k * 16, NF_ST);
#pragma unroll
        for (int nf = 0; nf < 8; nf++) {
            fragment<matrix_b, 16, 16, 16, __half, row_major> b;
            load_matrix_sync(b, sB + (k * 16) * NF_ST + nf * 16, NF_ST);
            mma_sync(acc[nf], a, b, acc[nf]);
        }
    }
    __syncthreads();

    {
        float* sD = (float*)smem;
#pragma unroll
        for (int nf = 0; nf < 8; nf++)
            store_matrix_sync(sD + m0 * 132 + nf * 16, acc[nf], 132, mem_row_major);
        __syncthreads();
        if (n < NN) {
#pragma unroll
            for (int q = 0; q < 16; q++) {
                int col = hf * 64 + q * 4;
                float4 v = *(const float4*)(sD + r * 132 + col);
                v.x += sB2[col + 0];
                v.y += sB2[col + 1];
                v.z += sB2[col + 2];
                v.w += sB2[col + 3];
                *(float4*)(hdst + (size_t)n * HID + col) = v;
            }
        }
    }
}

// ---------------- persistent edge kernel: B resident, half-width D epilogue ----------------
static constexpr int AST = 136;   // fp16 stride
static constexpr int ED_ST = 68;  // f32 stride, half-width D (unions A only)
static constexpr int SM_A  = 0;        // 34816; D [128][68] f32 = 34816 unions here
static constexpr int SM_B  = 34816;    // 34816 (persistent)
static constexpr int SM_WT = 69632;    // 2560  (persistent)
static constexpr int SM_B1 = 72192;    // 512   (persistent)
static constexpr int SM_B2 = 72704;    // 512   (persistent)
static constexpr int SM_ROW = 73216;   // 512   (per tile)
static constexpr int EDGE_SMEM_BYTES = 73728;

__global__ void __launch_bounds__(256, 2)
edge_hmma_kernel(const float* __restrict__ ew1, const float* __restrict__ eb1,
                 const float* __restrict__ eb2, int layer) {
    extern __shared__ char smem[];
    __half* sA = (__half*)(smem + SM_A);
    __half* sB = (__half*)(smem + SM_B);
    float* sD  = (float*)(smem + SM_A);
    float* sWT = (float*)(smem + SM_WT);
    float* sB1 = (float*)(smem + SM_B1);
    float* sB2 = (float*)(smem + SM_B2);
    int*   sRow = (int*)(smem + SM_ROW);

    int tid = threadIdx.x;
    int wid = tid >> 5;

    // one-time staging: B (cp.async), tail weights, biases
    {
        const __half* gW = g_Wf16[layer];
#pragma unroll
        for (int it = 0; it < 8; it++) {
            int i = tid + it * 256;
            int k = i >> 4, u = i & 15;
            cp16(sB + k * AST + u * 8, gW + k * HID + u * 8);
        }
        CP_COMMIT();
    }
    for (int i = tid; i < 5 * HID; i += 256) sWT[i] = ew1[(layer * 261 + 2 * HID) * HID + i];
    if (tid < HID) {
        sB1[tid] = eb1[layer * HID + tid];
        sB2[tid] = eb2[layer * HID + tid];
    }
    CP_WAIT0();
    __syncthreads();

    using namespace nvcuda::wmma;
    int m0 = (wid >> 1) * 32;
    int nb0 = (wid & 1) * 64;

    for (int tile = blockIdx.x; tile < NTILE; tile += gridDim.x) {
        int e0 = tile * 128;

        if (tid < 128) sRow[tid] = g_rowS[e0 + tid];
        __syncthreads();

        // A-build: elu(P1[row]+P2[col]+rad*w+ea@Wtail+b1) -> fp16
        {
            int m = tid >> 1, hf = tid & 1;
            int e = e0 + m;
            int r = sRow[m], c = g_colS[e];
            float rad = g_radS[e];
            float4 ea = g_eaS[e];
            const __half* p1r = g_P1h + (size_t)r * HID;
            const __half* p2r = g_P2h + (size_t)c * HID;
#pragma unroll
            for (int q = 0; q < 8; q++) {
                int jb = hf * 64 + q * 8;
                uint4 u1 = *(const uint4*)(p1r + jb);
                uint4 u2 = *(const uint4*)(p2r + jb);
                const __half2* h1 = (const __half2*)&u1;
                const __half2* h2 = (const __half2*)&u2;
                __half2* pa = (__half2*)(sA + m * AST + jb);
#pragma unroll
                for (int s = 0; s < 2; s++) {
                    int j4 = jb + s * 4;
                    float2 p1a = __half22float2(h1[s * 2 + 0]);
                    float2 p1b = __half22float2(h1[s * 2 + 1]);
                    float2 p2a = __half22float2(h2[s * 2 + 0]);
                    float2 p2b = __half22float2(h2[s * 2 + 1]);
                    float4 w0 = *(const float4*)(sWT + 0 * HID + j4);
                    float4 w1 = *(const float4*)(sWT + 1 * HID + j4);
                    float4 w2 = *(const float4*)(sWT + 2 * HID + j4);
                    float4 w3 = *(const float4*)(sWT + 3 * HID + j4);
                    float4 w4 = *(const float4*)(sWT + 4 * HID + j4);
                    float4 bb = *(const float4*)(sB1 + j4);
                    float o0 = elu(p1a.x + p2a.x + rad * w0.x + ea.x * w1.x + ea.y * w2.x + ea.z * w3.x + ea.w * w4.x + bb.x);
                    float o1 = elu(p1a.y + p2a.y + rad * w0.y + ea.x * w1.y + ea.y * w2.y + ea.z * w3.y + ea.w * w4.y + bb.y);
                    float o2 = elu(p1b.x + p2b.x + rad * w0.z + ea.x * w1.z + ea.y * w2.z + ea.z * w3.z + ea.w * w4.z + bb.z);
                    float o3 = elu(p1b.y + p2b.y + rad * w0.w + ea.x * w1.w + ea.y * w2.w + ea.z * w3.w + ea.w * w4.w + bb.w);
                    pa[s * 2 + 0] = __floats2half2_rn(o0, o1);
                    pa[s * 2 + 1] = __floats2half2_rn(o2, o3);
                }
            }
        }
        __syncthreads();

        // single-pass fp16 MMA: 2x4 warp grid
        fragment<accumulator, 16, 16, 16, float> acc[2][4];
#pragma unroll
        for (int i2 = 0; i2 < 2; i2++)
#pragma unroll
            for (int j = 0; j < 4; j++) fill_fragment(acc[i2][j], 0.f);

#pragma unroll
        for (int k = 0; k < 8; k++) {
            fragment<matrix_a, 16, 16, 16, __half, row_major> a0, a1;
            load_matrix_sync(a0, sA + m0 * AST + k * 16, AST);
            load_matrix_sync(a1, sA + (m0 + 16) * AST + k * 16, AST);
#pragma unroll
            for (int j = 0; j < 4; j++) {
                fragment<matrix_b, 16, 16, 16, __half, row_major> b;
                load_matrix_sync(b, sB + (k * 16) * AST + nb0 + j * 16, AST);
                mma_sync(acc[0][j], a0, b, acc[0][j]);
                mma_sync(acc[1][j], a1, b, acc[1][j]);
            }
        }
        __syncthreads();   // A dead -> half-width D may overwrite it

        // epilogue in two column halves (B preserved)
#pragma unroll
        for (int half = 0; half < 2; half++) {
            if ((wid & 1) == half) {
#pragma unroll
                for (int i2 = 0; i2 < 2; i2++)
#pragma unroll
                    for (int j = 0; j < 4; j++)
                        store_matrix_sync(sD + (m0 + i2 * 16) * ED_ST + j * 16,
                                          acc[i2][j], ED_ST, mem_row_major);
            }
            __syncthreads();

            // scatter: eg = 8-edge group, ct = 4-col group within this half
            {
                int ct = tid & 15, eg = tid >> 4;
                int jb = ct * 4;
                int gc = half * 64 + jb;
                float b0 = sB2[gc + 0], b1v = sB2[gc + 1];
                float b2v = sB2[gc + 2], b3v = sB2[gc + 3];
                float r0 = 0.f, r1 = 0.f, r2 = 0.f, r3 = 0.f;
                int cur = sRow[eg * 8];
#pragma unroll
                for (int i = 0; i < 8; i++) {
                    int m = eg * 8 + i;
                    int rr = sRow[m];
                    if (rr != cur) {
                        red4(g_agg + (size_t)cur * HID + gc, r0, r1, r2, r3);
                        r0 = r1 = r2 = r3 = 0.f;
                        cur = rr;
                    }
                    const float* sd = sD + m * ED_ST + jb;
                    r0 += elu(sd[0] + b0);
                    r1 += elu(sd[1] + b1v);
                    r2 += elu(sd[2] + b2v);
                    r3 += elu(sd[3] + b3v);
                }
                red4(g_agg + (size_t)cur * HID + gc, r0, r1, r2, r3);
            }
            __syncthreads();   // D half dead before next half / next tile
        }
    }
}

// ---------------- final head (vectorized) ----------------
__global__ void final_kernel(const float* __restrict__ label,
                             const float* __restrict__ eps,
                             const float* __restrict__ mu_w, const float* __restrict__ mu_b,
                             const float* __restrict__ var_w, const float* __restrict__ var_b,
                             float* __restrict__ out) {
    int idx = blockIdx.x * 256 + threadIdx.x;
    if (idx >= NN * 16) return;
    int n = idx >> 4, g = idx & 15;
    float4 am = *(const float4*)(mu_b + g * 4);
    float4 av = *(const float4*)(var_b + g * 4);
    const float* hrow = g_h0buf + (size_t)n * HID;
#pragma unroll 4
    for (int k = 0; k < HID; k++) {
        float hv = hrow[k];
        float4 mw = *(const float4*)(mu_w + k * LATD + g * 4);
        float4 vw = *(const float4*)(var_w + k * LATD + g * 4);
        am.x += hv * mw.x; am.y += hv * mw.y; am.z += hv * mw.z; am.w += hv * mw.w;
        av.x += hv * vw.x; av.y += hv * vw.y; av.z += hv * vw.z; av.w += hv * vw.w;
    }
#pragma unroll
    for (int c = 0; c < 7; c++) {
        float lv = label[n * 7 + c];
        float4 mw = *(const float4*)(mu_w + (HID + c) * LATD + g * 4);
        float4 vw = *(const float4*)(var_w + (HID + c) * LATD + g * 4);
        am.x += lv * mw.x; am.y += lv * mw.y; am.z += lv * mw.z; am.w += lv * mw.w;
        av.x += lv * vw.x; av.y += lv * vw.y; av.z += lv * vw.z; av.w += lv * vw.w;
    }
    float4 ep = *(const float4*)(eps + (size_t)n * LATD + g * 4);
    float4 o;
    o.x = am.x + 0.01f * ep.x * __expf(0.5f * av.x);
    o.y = am.y + 0.01f * ep.y * __expf(0.5f * av.y);
    o.z = am.z + 0.01f * ep.z * __expf(0.5f * av.z);
    o.w = am.w + 0.01f * ep.w * __expf(0.5f * av.w);
    *(float4*)(out + (size_t)n * LATD + g * 4) = o;
}

// ---------------- launch ----------------
extern "C" void kernel_launch(void* const* d_in, const int* in_sizes, int n_in,
                              void* d_out, int out_size) {
    const float* h0        = (const float*)d_in[0];
    const float* label     = (const float*)d_in[1];
    const float* x         = (const float*)d_in[2];
    const float* edge_attr = (const float*)d_in[3];
    const float* eps       = (const float*)d_in[4];
    const float* emb_w     = (const float*)d_in[5];
    const float* emb_b     = (const float*)d_in[6];
    const float* ew1       = (const float*)d_in[7];
    const float* eb1       = (const float*)d_in[8];
    const float* ew2       = (const float*)d_in[9];
    const float* eb2       = (const float*)d_in[10];
    const float* nw1       = (const float*)d_in[11];
    const float* nb1       = (const float*)d_in[12];
    const float* nw2       = (const float*)d_in[13];
    const float* nb2       = (const float*)d_in[14];
    const float* mu_w      = (const float*)d_in[15];
    const float* mu_b      = (const float*)d_in[16];
    const float* var_w     = (const float*)d_in[17];
    const float* var_b     = (const float*)d_in[18];
    const int*   edges     = (const int*)d_in[19];
    const int* rowp = edges;
    const int* colp = edges + NE;
    float* out = (float*)d_out;

    cudaFuncSetAttribute(edge_hmma_kernel, cudaFuncAttributeMaxDynamicSharedMemorySize, EDGE_SMEM_BYTES);
    cudaFuncSetAttribute(pre_f16_kernel, cudaFuncAttributeMaxDynamicSharedMemorySize, PRE_SMEM);
    cudaFuncSetAttribute(node_f16_kernel, cudaFuncAttributeMaxDynamicSharedMemorySize, NODE_SMEM);

    const int GGRID = (NN + 127) / 128;   // 391

    embed_kernel<<<(NN * HID + 255) / 256, 256>>>(h0, emb_w, emb_b, ew2, ew1, nw1, nw2);

    sort_hist_kernel<<<(NE + 255) / 256, 256>>>(rowp);
    sort_scan1_kernel<<<NB_SCAN, 512>>>();
    sort_scan3_kernel<<<(NN + 255) / 256, 256>>>();
    sort_scatter_kernel<<<(NE + 255) / 256, 256>>>(rowp, colp, x, edge_attr);

    float *h0p, *h1p, *aggp;
    cudaGetSymbolAddress((void**)&h0p, g_h0buf);
    cudaGetSymbolAddress((void**)&h1p, g_h1buf);
    cudaGetSymbolAddress((void**)&aggp, g_agg);
    __half *p1p, *p2p, *e1f, *n1f, *n2f;
    cudaGetSymbolAddress((void**)&p1p, g_P1h);
    cudaGetSymbolAddress((void**)&p2p, g_P2h);
    cudaGetSymbolAddress((void**)&e1f, g_E1f16);
    cudaGetSymbolAddress((void**)&n1f, g_N1f16);
    cudaGetSymbolAddress((void**)&n2f, g_N2f16);

    for (int layer = 0; layer < 2; layer++) {
        float* hsrc_p = (layer == 0) ? h0p : h1p;
        float* hdst   = (layer == 0) ? h1p : h0p;

        pre_f16_kernel<<<GGRID, 256, PRE_SMEM>>>(
            hsrc_p,
            e1f + (size_t)layer * 2 * HID * HID, p1p,
            e1f + ((size_t)layer * 2 + 1) * HID * HID, p2p);

        edge_hmma_kernel<<<EGRID, 256, EDGE_SMEM_BYTES>>>(ew1, eb1, eb2, layer);

        node_f16_kernel<<<GGRID, 256, NODE_SMEM>>>(
            hsrc_p, aggp,
            n1f + (size_t)layer * 2 * HID * HID,
            n2f + (size_t)layer * HID * HID,
            nb1 + layer * HID, nb2 + layer * HID, hdst);
    }

    final_kernel<<<(NN * 16 + 255) / 256, 256>>>(label, eps, mu_w, mu_b,
                                                 var_w, var_b, out);
}